// round 10
// baseline (speedup 1.0000x reference)
#include <cuda_runtime.h>
#include <cuda.h>
#include <cuda_bf16.h>
#include <cstdint>
#include <math.h>

#define Bx 4
#define Sx 1024
#define Dx 1024
#define Hx 16
#define HDx 64
#define TDx 3072
#define SCS 1028   // scores smem row stride (== 4 mod 32 -> conflict-free frags)

__device__ float g_qkv[Bx * Sx * TDx];
__device__ float g_aout[Bx * Sx * Dx];
__device__ float g_xr[Bx * Sx * Dx];
__device__ float g_war[Dx * TDx];
__device__ float g_wpr[Dx * Dx];
__device__ float g_kT[Bx * Hx * Sx * HDx];   // [bh][j][d] tf32 K
__device__ float g_vT[Bx * Hx * HDx * Sx];   // [bh][d][j] tf32 V^T

// ---------------------------------------------------------------------------
__device__ __forceinline__ unsigned f2tf32(float f) {
    unsigned r;
    asm("cvt.rna.tf32.f32 %0, %1;" : "=r"(r) : "f"(f));
    return r;
}
__device__ __forceinline__ float tf32f(float f) { return __uint_as_float(f2tf32(f)); }

__device__ __forceinline__ void mma_tf32(float c[4], const unsigned a[4], const unsigned b[2]) {
    asm volatile("mma.sync.aligned.m16n8k8.row.col.f32.tf32.tf32.f32 "
        "{%0,%1,%2,%3}, {%4,%5,%6,%7}, {%8,%9}, {%0,%1,%2,%3};"
        : "+f"(c[0]), "+f"(c[1]), "+f"(c[2]), "+f"(c[3])
        : "r"(a[0]), "r"(a[1]), "r"(a[2]), "r"(a[3]), "r"(b[0]), "r"(b[1]));
}

__device__ __forceinline__ float expapx(float x) {
    float y = fmaxf(x * 1.4426950408889634f, -80.f);
    float t = y + 12582912.f;
    int   n = __float_as_int(t) - 0x4b400000;
    float f = y - (t - 12582912.f);
    float p = 1.3333558146428443e-3f;
    p = fmaf(p, f, 9.618129842118066e-3f);
    p = fmaf(p, f, 5.550410866482158e-2f);
    p = fmaf(p, f, 2.402265069591007e-1f);
    p = fmaf(p, f, 6.931471805599453e-1f);
    p = fmaf(p, f, 1.0f);
    return __int_as_float(__float_as_int(p) + (n << 23));
}

#define CP16(dst, src) asm volatile("cp.async.cg.shared.global [%0], [%1], 16;" :: "r"(dst), "l"(src))
#define CP_COMMIT()    asm volatile("cp.async.commit_group;")
#define CP_WAIT1()     asm volatile("cp.async.wait_group 1;")
#define CP_WAIT0()     asm volatile("cp.async.wait_group 0;")
#define BARP()         asm volatile("bar.sync 1, 256;" ::: "memory")

// ---------------------------------------------------------------------------
__global__ void round_tf32(const float* __restrict__ in, float* __restrict__ out, int n4) {
    int i = blockIdx.x * blockDim.x + threadIdx.x;
    if (i < n4) {
        float4 v = ((const float4*)in)[i];
        uint4 o;
        o.x = f2tf32(v.x); o.y = f2tf32(v.y); o.z = f2tf32(v.z); o.w = f2tf32(v.w);
        ((uint4*)out)[i] = o;
    }
}

// kT[bh][j][d] = tf32(K)
__global__ void prep_kT(const float* __restrict__ qkv, float* __restrict__ kT) {
    int i = blockIdx.x * 256 + threadIdx.x;
    int c = i & 15, j = (i >> 4) & 1023, bh = i >> 14;
    int b = bh >> 4, h = bh & 15;
    float4 v = *(const float4*)&qkv[((size_t)(b * Sx + j)) * TDx + Dx + h * HDx + c * 4];
    uint4 o = {f2tf32(v.x), f2tf32(v.y), f2tf32(v.z), f2tf32(v.w)};
    *(uint4*)&kT[(size_t)i * 4] = o;
}

// vT[bh][d][j] = tf32(V)
__global__ void prep_vT(const float* __restrict__ qkv, float* __restrict__ vT) {
    __shared__ float tile[64][68];
    int bh = blockIdx.y, j0 = blockIdx.x * 64;
    int b = bh >> 4, h = bh & 15;
    int t = threadIdx.x;
    #pragma unroll
    for (int i = 0; i < 4; i++) {
        int id = t + i * 256;
        int jj = id >> 4, c = id & 15;
        float4 v = *(const float4*)&qkv[((size_t)(b * Sx + j0 + jj)) * TDx + 2 * Dx + h * HDx + c * 4];
        tile[jj][c * 4 + 0] = tf32f(v.x);
        tile[jj][c * 4 + 1] = tf32f(v.y);
        tile[jj][c * 4 + 2] = tf32f(v.z);
        tile[jj][c * 4 + 3] = tf32f(v.w);
    }
    __syncthreads();
    #pragma unroll
    for (int i = 0; i < 4; i++) {
        int id = t + i * 256;
        int d = id >> 4, c = id & 15;
        float4 o = {tile[c * 4 + 0][d], tile[c * 4 + 1][d], tile[c * 4 + 2][d], tile[c * 4 + 3][d]};
        *(float4*)&vT[((size_t)(bh * HDx + d)) * Sx + j0 + c * 4] = o;
    }
}

// ---------------------------------------------------------------------------
// tf32 GEMM, 3-stage cp.async pipeline, one barrier per k-tile.
// __launch_bounds__(256,3): target 3 CTAs/SM.
// ---------------------------------------------------------------------------
#define GEMM_SMEM 56832
__global__ __launch_bounds__(256, 3) void gemm_mma(const float* __restrict__ A,
                                                   const float* __restrict__ B,
                                                   const float* __restrict__ bias,
                                                   float* __restrict__ C,
                                                   int M, int N, int K) {
    extern __shared__ float gsm[];
    float* Asb = gsm;                 // 3 stages of [128][20]
    float* Bsb = gsm + 3 * 2560;      // 3 stages of [16][136]

    const int t = threadIdx.x;
    const int warp = t >> 5, lane = t & 31;
    const int wm = warp >> 2, wn = warp & 3;
    const int r = lane >> 2, cq = lane & 3;
    const int row0 = blockIdx.y * 128, col0 = blockIdx.x * 128;

    float acc[4][4][4];
    #pragma unroll
    for (int i = 0; i < 4; i++)
        #pragma unroll
        for (int j = 0; j < 4; j++)
            #pragma unroll
            for (int k = 0; k < 4; k++) acc[i][j][k] = 0.f;

    const int aM0 = (t * 2) >> 2,  aK0 = (t * 2) & 3;
    const int aM1 = (t * 2 + 1) >> 2, aK1 = (t * 2 + 1) & 3;
    const int bK0 = (t * 2) >> 5,  bN0 = (t * 2) & 31;
    const int bK1 = (t * 2 + 1) >> 5, bN1 = (t * 2 + 1) & 31;

    auto loadG = [&](int st, int k0) {
        float* As = Asb + st * 2560;
        float* Bs = Bsb + st * 2176;
        unsigned da0 = (unsigned)__cvta_generic_to_shared(&As[aM0 * 20 + aK0 * 4]);
        unsigned da1 = (unsigned)__cvta_generic_to_shared(&As[aM1 * 20 + aK1 * 4]);
        CP16(da0, &A[(size_t)(row0 + aM0) * K + k0 + aK0 * 4]);
        CP16(da1, &A[(size_t)(row0 + aM1) * K + k0 + aK1 * 4]);
        unsigned db0 = (unsigned)__cvta_generic_to_shared(&Bs[bK0 * 136 + bN0 * 4]);
        unsigned db1 = (unsigned)__cvta_generic_to_shared(&Bs[bK1 * 136 + bN1 * 4]);
        CP16(db0, &B[(size_t)(k0 + bK0) * N + col0 + bN0 * 4]);
        CP16(db1, &B[(size_t)(k0 + bK1) * N + col0 + bN1 * 4]);
    };

    loadG(0, 0);  CP_COMMIT();
    loadG(1, 16); CP_COMMIT();

    const int NT = K / 16;
    int st = 0;
    for (int kt = 0; kt < NT; kt++) {
        if (kt + 1 < NT) CP_WAIT1(); else CP_WAIT0();
        __syncthreads();
        if (kt + 2 < NT) {
            int st2 = st + 2; if (st2 >= 3) st2 -= 3;
            loadG(st2, (kt + 2) * 16);
            CP_COMMIT();
        }
        const float* As = Asb + st * 2560;
        const float* Bs = Bsb + st * 2176;

        #pragma unroll
        for (int ks = 0; ks < 2; ks++) {
            const int kb = ks * 8;
            unsigned a[4][4], b[4][2];
            #pragma unroll
            for (int mm = 0; mm < 4; mm++) {
                const float* ap0 = &As[(wm * 64 + mm * 16 + r) * 20 + kb + cq];
                const float* ap1 = ap0 + 8 * 20;
                a[mm][0] = __float_as_uint(ap0[0]);
                a[mm][1] = __float_as_uint(ap1[0]);
                a[mm][2] = __float_as_uint(ap0[4]);
                a[mm][3] = __float_as_uint(ap1[4]);
            }
            #pragma unroll
            for (int nn = 0; nn < 4; nn++) {
                const float* bp = &Bs[(kb + cq) * 136 + wn * 32 + nn * 8 + r];
                b[nn][0] = __float_as_uint(bp[0]);
                b[nn][1] = __float_as_uint(bp[4 * 136]);
            }
            #pragma unroll
            for (int mm = 0; mm < 4; mm++)
                #pragma unroll
                for (int nn = 0; nn < 4; nn++)
                    mma_tf32(acc[mm][nn], a[mm], b[nn]);
        }
        if (++st == 3) st = 0;
    }

    #pragma unroll
    for (int mm = 0; mm < 4; mm++) {
        int r0 = row0 + wm * 64 + mm * 16 + r;
        #pragma unroll
        for (int nn = 0; nn < 4; nn++) {
            int c0 = col0 + wn * 32 + nn * 8 + 2 * cq;
            float2 bv = *(const float2*)&bias[c0];
            float2 o0 = {acc[mm][nn][0] + bv.x, acc[mm][nn][1] + bv.y};
            float2 o1 = {acc[mm][nn][2] + bv.x, acc[mm][nn][3] + bv.y};
            *(float2*)&C[(size_t)r0 * N + c0] = o0;
            *(float2*)&C[(size_t)(r0 + 8) * N + c0] = o1;
        }
    }
}

// ---------------------------------------------------------------------------
// Tensor-core attention, 512 threads. After the scores phase, warps 0-7 do
// rowsum + normalized w store while warps 8-15 run the PV mma loop
// (warp-specialized overlap; PV half synced with bar.sync 1,256).
// ---------------------------------------------------------------------------
__global__ __launch_bounds__(512) void attn_mma(const float* __restrict__ qkv,
                                                const float* __restrict__ kT,
                                                const float* __restrict__ vT,
                                                const float* __restrict__ mask,
                                                float* __restrict__ w_out,
                                                float* __restrict__ aout) {
    extern __shared__ float sm[];
    float* sc   = sm;            // [32][SCS]
    float* qs   = sm + 32896;    // [32][68]
    float* kvb  = sm + 35072;    // 2 x 8704
    float* mks  = sm + 52480;    // [1024]
    float* invs = sm + 53504;    // [32]

    const int q0 = blockIdx.x * 32;
    const int h  = blockIdx.y;
    const int b  = blockIdx.z;
    const int bh = b * Hx + h;
    const int t  = threadIdx.x;
    const int warp = t >> 5, lane = t & 31;
    const int r = lane >> 2, cq = lane & 3;
    const int wm = warp >> 3;       // scores: 2(M) x 8(N)
    const int wn = warp & 7;
    const float* base = qkv + (size_t)b * Sx * TDx;
    const float* kTb = kT + (size_t)bh * Sx * HDx;
    const float* vTb = vT + (size_t)bh * HDx * Sx;

    auto stageK = [&](int buf, int j0) {
        float* dstb = kvb + buf * 8704;
        #pragma unroll
        for (int i = 0; i < 4; i++) {
            int id = t + i * 512;
            int jj = id >> 4, c = id & 15;
            unsigned d = (unsigned)__cvta_generic_to_shared(&dstb[jj * 68 + c * 4]);
            CP16(d, &kTb[(size_t)(j0 + jj) * HDx + c * 4]);
        }
    };
    // V staged by PV half only (threads 256..511)
    auto stageV = [&](int buf, int j0) {
        float* dstb = kvb + buf * 8704;
        int t2 = t - 256;
        #pragma unroll
        for (int i = 0; i < 8; i++) {
            int id = t2 + i * 256;
            int dd = id >> 5, c = id & 31;
            unsigned d = (unsigned)__cvta_generic_to_shared(&dstb[dd * 132 + c * 4]);
            CP16(d, &vTb[(size_t)dd * Sx + j0 + c * 4]);
        }
    };

    if (t < 256) *(float4*)&mks[4 * t] = *(const float4*)&mask[b * Sx + 4 * t];
    #pragma unroll
    for (int i = 0; i < 4; i++) {
        int id = t + i * 512;
        int rr = id >> 6, d = id & 63;
        qs[rr * 68 + d] = tf32f(base[(size_t)(q0 + rr) * TDx + h * HDx + d]);
    }

    const int ntile = (q0 + 31) / 128 + 1;
    const int Ccols = ntile * 128;

    stageK(0, 0);
    CP_COMMIT();
    __syncthreads();

    // ---- scores ----
    for (int jt = 0; jt < ntile; jt++) {
        const int j0 = jt * 128;
        if (jt + 1 < ntile) { stageK((jt + 1) & 1, (jt + 1) * 128); CP_COMMIT(); CP_WAIT1(); }
        else                { CP_WAIT0(); }
        __syncthreads();
        const float* kvt = kvb + (jt & 1) * 8704;

        float c[2][4];
        #pragma unroll
        for (int i = 0; i < 2; i++)
            #pragma unroll
            for (int j = 0; j < 4; j++) c[i][j] = 0.f;

        #pragma unroll
        for (int ks = 0; ks < 8; ks++) {
            const int kb = ks * 8;
            unsigned a[4];
            const float* ap0 = &qs[(wm * 16 + r) * 68 + kb + cq];
            const float* ap1 = ap0 + 8 * 68;
            a[0] = __float_as_uint(ap0[0]);
            a[1] = __float_as_uint(ap1[0]);
            a[2] = __float_as_uint(ap0[4]);
            a[3] = __float_as_uint(ap1[4]);
            #pragma unroll
            for (int nn = 0; nn < 2; nn++) {
                const float* bp = &kvt[(wn * 16 + nn * 8 + r) * 68 + kb + cq];
                unsigned bf[2] = {__float_as_uint(bp[0]), __float_as_uint(bp[4])};
                mma_tf32(c[nn], a, bf);
            }
        }

        const int qa = q0 + wm * 16 + r;
        const int qb = qa + 8;
        #pragma unroll
        for (int nn = 0; nn < 2; nn++) {
            int jl = wn * 16 + nn * 8 + 2 * cq;
            int jg = j0 + jl;
            float mk0 = mks[jg], mk1 = mks[jg + 1];
            float* s0 = &sc[(wm * 16 + r) * SCS + jg];
            float* s1 = &sc[(wm * 16 + r + 8) * SCS + jg];
            s0[0] = (jg     <= qa) ? tf32f(expapx(fmaf(c[nn][0], 0.125f, mk0))) : 0.f;
            s0[1] = (jg + 1 <= qa) ? tf32f(expapx(fmaf(c[nn][1], 0.125f, mk1))) : 0.f;
            s1[0] = (jg     <= qb) ? tf32f(expapx(fmaf(c[nn][2], 0.125f, mk0))) : 0.f;
            s1[1] = (jg + 1 <= qb) ? tf32f(expapx(fmaf(c[nn][3], 0.125f, mk1))) : 0.f;
        }
        __syncthreads();
    }
    // sc complete for all warps here.

    float oc[2][4];
    #pragma unroll
    for (int i = 0; i < 2; i++)
        #pragma unroll
        for (int j = 0; j < 4; j++) oc[i][j] = 0.f;

    if (warp < 8) {
        // ---- w-store half: rowsum + normalized w store + zero fill ----
        #pragma unroll
        for (int rr = 0; rr < 4; rr++) {
            int row = warp * 4 + rr;
            int q = q0 + row;
            float s = 0.f;
            for (int j4 = lane * 4; j4 < Ccols; j4 += 128) {
                float4 v = *(float4*)&sc[row * SCS + j4];
                s += v.x + v.y + v.z + v.w;
            }
            #pragma unroll
            for (int o = 16; o > 0; o >>= 1) s += __shfl_xor_sync(0xffffffffu, s, o);
            float inv = 1.f / s;
            if (lane == 0) invs[row] = inv;
            size_t wb = ((size_t)(bh * Sx + q)) * Sx;
            for (int j4 = lane * 4; j4 < Ccols; j4 += 128) {
                float4 v = *(float4*)&sc[row * SCS + j4];
                float4 o4 = {v.x * inv, v.y * inv, v.z * inv, v.w * inv};
                *(float4*)&w_out[wb + j4] = o4;
            }
            float4 z = {0.f, 0.f, 0.f, 0.f};
            for (int j4 = Ccols + lane * 4; j4 < Sx; j4 += 128)
                *(float4*)&w_out[wb + j4] = z;
        }
    } else {
        // ---- PV half: 8 warps, 2(M) x 4(N of 16 cols) ----
        const int pwm = (warp - 8) >> 2;
        const int pwn = (warp - 8) & 3;

        stageV(0, 0);
        CP_COMMIT();

        for (int jt = 0; jt < ntile; jt++) {
            const int j0 = jt * 128;
            if (jt + 1 < ntile) { stageV((jt + 1) & 1, (jt + 1) * 128); CP_COMMIT(); CP_WAIT1(); }
            else                { CP_WAIT0(); }
            BARP();
            const float* kvt = kvb + (jt & 1) * 8704;

            #pragma unroll
            for (int ks = 0; ks < 16; ks++) {
                const int kb = ks * 8;
                unsigned a[4];
                const float* ap0 = &sc[(pwm * 16 + r) * SCS + j0 + kb + cq];
                const float* ap1 = ap0 + 8 * SCS;
                a[0] = __float_as_uint(ap0[0]);
                a[1] = __float_as_uint(ap1[0]);
                a[2] = __float_as_uint(ap0[4]);
                a[3] = __float_as_uint(ap1[4]);
                #pragma unroll
                for (int nn = 0; nn < 2; nn++) {
                    const float* bp = &kvt[(pwn * 16 + nn * 8 + r) * 132 + kb + cq];
                    unsigned bf[2] = {__float_as_uint(bp[0]), __float_as_uint(bp[4])};
                    mma_tf32(oc[nn], a, bf);
                }
            }
            BARP();
        }
    }
    __syncthreads();   // invs ready, PV done

    if (warp >= 8) {
        const int pwm = (warp - 8) >> 2;
        const int pwn = (warp - 8) & 3;
        int row_a = pwm * 16 + r, row_b = row_a + 8;
        float ia = invs[row_a], ib = invs[row_b];
        #pragma unroll
        for (int nn = 0; nn < 2; nn++) {
            int d = pwn * 16 + nn * 8 + 2 * cq;
            size_t ra = ((size_t)(b * Sx + q0 + row_a)) * Dx + h * HDx + d;
            size_t rb = ((size_t)(b * Sx + q0 + row_b)) * Dx + h * HDx + d;
            float2 v0 = {tf32f(oc[nn][0] * ia), tf32f(oc[nn][1] * ia)};
            float2 v1 = {tf32f(oc[nn][2] * ib), tf32f(oc[nn][3] * ib)};
            *(float2*)&aout[ra] = v0;
            *(float2*)&aout[rb] = v1;
        }
    }
}

// ---------------------------------------------------------------------------
extern "C" void kernel_launch(void* const* d_in, const int* in_sizes, int n_in,
                              void* d_out, int out_size) {
    const float* x      = (const float*)d_in[0];
    const float* mask   = (const float*)d_in[1];
    const float* w_attn = (const float*)d_in[2];
    const float* b_attn = (const float*)d_in[3];
    const float* w_proj = (const float*)d_in[4];
    const float* b_proj = (const float*)d_in[5];

    float* out_a = (float*)d_out;
    float* out_w = (float*)d_out + (size_t)Bx * Sx * Dx;

    float *qkv, *aout, *xr, *war, *wpr, *kT, *vT;
    cudaGetSymbolAddress((void**)&qkv,  g_qkv);
    cudaGetSymbolAddress((void**)&aout, g_aout);
    cudaGetSymbolAddress((void**)&xr,   g_xr);
    cudaGetSymbolAddress((void**)&war,  g_war);
    cudaGetSymbolAddress((void**)&wpr,  g_wpr);
    cudaGetSymbolAddress((void**)&kT,   g_kT);
    cudaGetSymbolAddress((void**)&vT,   g_vT);

    static const int ATTN_SMEM = 53536 * 4;   // 214144 B
    cudaFuncSetAttribute(attn_mma, cudaFuncAttributeMaxDynamicSharedMemorySize, ATTN_SMEM);
    cudaFuncSetAttribute(gemm_mma, cudaFuncAttributeMaxDynamicSharedMemorySize, GEMM_SMEM);

    {
        int n;
        n = Bx * Sx * Dx / 4;  round_tf32<<<(n + 255) / 256, 256>>>(x, xr, n);
        n = Dx * TDx / 4;      round_tf32<<<(n + 255) / 256, 256>>>(w_attn, war, n);
        n = Dx * Dx / 4;       round_tf32<<<(n + 255) / 256, 256>>>(w_proj, wpr, n);
    }
    {
        dim3 grid(TDx / 128, (Bx * Sx) / 128);
        gemm_mma<<<grid, 256, GEMM_SMEM>>>(xr, war, b_attn, qkv, Bx * Sx, TDx, Dx);
    }
    {
        prep_kT<<<(Bx * Hx * Sx * 16) / 256, 256>>>(qkv, kT);
        dim3 gv(Sx / 64, Bx * Hx);
        prep_vT<<<gv, 256>>>(qkv, vT);
    }
    {
        dim3 grid(Sx / 32, Hx, Bx);
        attn_mma<<<grid, 512, ATTN_SMEM>>>(qkv, kT, vT, mask, out_w, aout);
    }
    {
        dim3 grid(Dx / 128, (Bx * Sx) / 128);
        gemm_mma<<<grid, 256, GEMM_SMEM>>>(aout, wpr, b_proj, out_a, Bx * Sx, Dx, Dx);
    }
}

// round 11
// speedup vs baseline: 1.4712x; 1.4712x over previous
#include <cuda_runtime.h>
#include <cuda.h>
#include <cuda_bf16.h>
#include <cstdint>
#include <math.h>

#define Bx 4
#define Sx 1024
#define Dx 1024
#define Hx 16
#define HDx 64
#define TDx 3072
#define SCS 1028   // scores smem row stride (== 4 mod 32 -> conflict-free frags)

__device__ float g_qkv[Bx * Sx * TDx];
__device__ float g_aout[Bx * Sx * Dx];
__device__ float g_xr[Bx * Sx * Dx];
__device__ float g_war[Dx * TDx];
__device__ float g_wpr[Dx * Dx];
__device__ float g_kT[Bx * Hx * Sx * HDx];   // [bh][j][d] tf32 K
__device__ float g_vT[Bx * Hx * HDx * Sx];   // [bh][d][j] tf32 V^T

// ---------------------------------------------------------------------------
__device__ __forceinline__ unsigned f2tf32(float f) {
    unsigned r;
    asm("cvt.rna.tf32.f32 %0, %1;" : "=r"(r) : "f"(f));
    return r;
}
__device__ __forceinline__ float tf32f(float f) { return __uint_as_float(f2tf32(f)); }

__device__ __forceinline__ void mma_tf32(float c[4], const unsigned a[4], const unsigned b[2]) {
    asm volatile("mma.sync.aligned.m16n8k8.row.col.f32.tf32.tf32.f32 "
        "{%0,%1,%2,%3}, {%4,%5,%6,%7}, {%8,%9}, {%0,%1,%2,%3};"
        : "+f"(c[0]), "+f"(c[1]), "+f"(c[2]), "+f"(c[3])
        : "r"(a[0]), "r"(a[1]), "r"(a[2]), "r"(a[3]), "r"(b[0]), "r"(b[1]));
}

__device__ __forceinline__ float expapx(float x) {
    float y = fmaxf(x * 1.4426950408889634f, -80.f);
    float t = y + 12582912.f;
    int   n = __float_as_int(t) - 0x4b400000;
    float f = y - (t - 12582912.f);
    float p = 1.3333558146428443e-3f;
    p = fmaf(p, f, 9.618129842118066e-3f);
    p = fmaf(p, f, 5.550410866482158e-2f);
    p = fmaf(p, f, 2.402265069591007e-1f);
    p = fmaf(p, f, 6.931471805599453e-1f);
    p = fmaf(p, f, 1.0f);
    return __int_as_float(__float_as_int(p) + (n << 23));
}

#define CP16(dst, src) asm volatile("cp.async.cg.shared.global [%0], [%1], 16;" :: "r"(dst), "l"(src))
#define CP_COMMIT()    asm volatile("cp.async.commit_group;")
#define CP_WAIT1()     asm volatile("cp.async.wait_group 1;")
#define CP_WAIT0()     asm volatile("cp.async.wait_group 0;")
#define BARP()         asm volatile("bar.sync 1, 256;" ::: "memory")

// ---------------------------------------------------------------------------
__global__ void round_tf32(const float* __restrict__ in, float* __restrict__ out, int n4) {
    int i = blockIdx.x * blockDim.x + threadIdx.x;
    if (i < n4) {
        float4 v = ((const float4*)in)[i];
        uint4 o;
        o.x = f2tf32(v.x); o.y = f2tf32(v.y); o.z = f2tf32(v.z); o.w = f2tf32(v.w);
        ((uint4*)out)[i] = o;
    }
}

// kT[bh][j][d] = tf32(K)
__global__ void prep_kT(const float* __restrict__ qkv, float* __restrict__ kT) {
    int i = blockIdx.x * 256 + threadIdx.x;
    int c = i & 15, j = (i >> 4) & 1023, bh = i >> 14;
    int b = bh >> 4, h = bh & 15;
    float4 v = *(const float4*)&qkv[((size_t)(b * Sx + j)) * TDx + Dx + h * HDx + c * 4];
    uint4 o = {f2tf32(v.x), f2tf32(v.y), f2tf32(v.z), f2tf32(v.w)};
    *(uint4*)&kT[(size_t)i * 4] = o;
}

// vT[bh][d][j] = tf32(V)
__global__ void prep_vT(const float* __restrict__ qkv, float* __restrict__ vT) {
    __shared__ float tile[64][68];
    int bh = blockIdx.y, j0 = blockIdx.x * 64;
    int b = bh >> 4, h = bh & 15;
    int t = threadIdx.x;
    #pragma unroll
    for (int i = 0; i < 4; i++) {
        int id = t + i * 256;
        int jj = id >> 4, c = id & 15;
        float4 v = *(const float4*)&qkv[((size_t)(b * Sx + j0 + jj)) * TDx + 2 * Dx + h * HDx + c * 4];
        tile[jj][c * 4 + 0] = tf32f(v.x);
        tile[jj][c * 4 + 1] = tf32f(v.y);
        tile[jj][c * 4 + 2] = tf32f(v.z);
        tile[jj][c * 4 + 3] = tf32f(v.w);
    }
    __syncthreads();
    #pragma unroll
    for (int i = 0; i < 4; i++) {
        int id = t + i * 256;
        int d = id >> 4, c = id & 15;
        float4 o = {tile[c * 4 + 0][d], tile[c * 4 + 1][d], tile[c * 4 + 2][d], tile[c * 4 + 3][d]};
        *(float4*)&vT[((size_t)(bh * HDx + d)) * Sx + j0 + c * 4] = o;
    }
}

// ---------------------------------------------------------------------------
// tf32 GEMM, 3-stage cp.async pipeline, one barrier per k-tile.
// R7 configuration: no minCTAs clause (regs ~96, no spills).
// ---------------------------------------------------------------------------
#define GEMM_SMEM 56832
__global__ __launch_bounds__(256) void gemm_mma(const float* __restrict__ A,
                                                const float* __restrict__ B,
                                                const float* __restrict__ bias,
                                                float* __restrict__ C,
                                                int M, int N, int K) {
    extern __shared__ float gsm[];
    float* Asb = gsm;                 // 3 stages of [128][20]
    float* Bsb = gsm + 3 * 2560;      // 3 stages of [16][136]

    const int t = threadIdx.x;
    const int warp = t >> 5, lane = t & 31;
    const int wm = warp >> 2, wn = warp & 3;
    const int r = lane >> 2, cq = lane & 3;
    const int row0 = blockIdx.y * 128, col0 = blockIdx.x * 128;

    float acc[4][4][4];
    #pragma unroll
    for (int i = 0; i < 4; i++)
        #pragma unroll
        for (int j = 0; j < 4; j++)
            #pragma unroll
            for (int k = 0; k < 4; k++) acc[i][j][k] = 0.f;

    const int aM0 = (t * 2) >> 2,  aK0 = (t * 2) & 3;
    const int aM1 = (t * 2 + 1) >> 2, aK1 = (t * 2 + 1) & 3;
    const int bK0 = (t * 2) >> 5,  bN0 = (t * 2) & 31;
    const int bK1 = (t * 2 + 1) >> 5, bN1 = (t * 2 + 1) & 31;

    auto loadG = [&](int st, int k0) {
        float* As = Asb + st * 2560;
        float* Bs = Bsb + st * 2176;
        unsigned da0 = (unsigned)__cvta_generic_to_shared(&As[aM0 * 20 + aK0 * 4]);
        unsigned da1 = (unsigned)__cvta_generic_to_shared(&As[aM1 * 20 + aK1 * 4]);
        CP16(da0, &A[(size_t)(row0 + aM0) * K + k0 + aK0 * 4]);
        CP16(da1, &A[(size_t)(row0 + aM1) * K + k0 + aK1 * 4]);
        unsigned db0 = (unsigned)__cvta_generic_to_shared(&Bs[bK0 * 136 + bN0 * 4]);
        unsigned db1 = (unsigned)__cvta_generic_to_shared(&Bs[bK1 * 136 + bN1 * 4]);
        CP16(db0, &B[(size_t)(k0 + bK0) * N + col0 + bN0 * 4]);
        CP16(db1, &B[(size_t)(k0 + bK1) * N + col0 + bN1 * 4]);
    };

    loadG(0, 0);  CP_COMMIT();
    loadG(1, 16); CP_COMMIT();

    const int NT = K / 16;
    int st = 0;
    for (int kt = 0; kt < NT; kt++) {
        if (kt + 1 < NT) CP_WAIT1(); else CP_WAIT0();
        __syncthreads();
        if (kt + 2 < NT) {
            int st2 = st + 2; if (st2 >= 3) st2 -= 3;
            loadG(st2, (kt + 2) * 16);
            CP_COMMIT();
        }
        const float* As = Asb + st * 2560;
        const float* Bs = Bsb + st * 2176;

        #pragma unroll
        for (int ks = 0; ks < 2; ks++) {
            const int kb = ks * 8;
            unsigned a[4][4], b[4][2];
            #pragma unroll
            for (int mm = 0; mm < 4; mm++) {
                const float* ap0 = &As[(wm * 64 + mm * 16 + r) * 20 + kb + cq];
                const float* ap1 = ap0 + 8 * 20;
                a[mm][0] = __float_as_uint(ap0[0]);
                a[mm][1] = __float_as_uint(ap1[0]);
                a[mm][2] = __float_as_uint(ap0[4]);
                a[mm][3] = __float_as_uint(ap1[4]);
            }
            #pragma unroll
            for (int nn = 0; nn < 4; nn++) {
                const float* bp = &Bs[(kb + cq) * 136 + wn * 32 + nn * 8 + r];
                b[nn][0] = __float_as_uint(bp[0]);
                b[nn][1] = __float_as_uint(bp[4 * 136]);
            }
            #pragma unroll
            for (int mm = 0; mm < 4; mm++)
                #pragma unroll
                for (int nn = 0; nn < 4; nn++)
                    mma_tf32(acc[mm][nn], a[mm], b[nn]);
        }
        if (++st == 3) st = 0;
    }

    #pragma unroll
    for (int mm = 0; mm < 4; mm++) {
        int r0 = row0 + wm * 64 + mm * 16 + r;
        #pragma unroll
        for (int nn = 0; nn < 4; nn++) {
            int c0 = col0 + wn * 32 + nn * 8 + 2 * cq;
            float2 bv = *(const float2*)&bias[c0];
            float2 o0 = {acc[mm][nn][0] + bv.x, acc[mm][nn][1] + bv.y};
            float2 o1 = {acc[mm][nn][2] + bv.x, acc[mm][nn][3] + bv.y};
            *(float2*)&C[(size_t)r0 * N + c0] = o0;
            *(float2*)&C[(size_t)(r0 + 8) * N + c0] = o1;
        }
    }
}

// ---------------------------------------------------------------------------
// Tensor-core attention, 512 threads. After the scores phase, warps 0-7 do
// rowsum + normalized w store while warps 8-15 run the PV mma loop
// (warp-specialized overlap; PV half synced with bar.sync 1,256).
// ---------------------------------------------------------------------------
__global__ __launch_bounds__(512) void attn_mma(const float* __restrict__ qkv,
                                                const float* __restrict__ kT,
                                                const float* __restrict__ vT,
                                                const float* __restrict__ mask,
                                                float* __restrict__ w_out,
                                                float* __restrict__ aout) {
    extern __shared__ float sm[];
    float* sc   = sm;            // [32][SCS]
    float* qs   = sm + 32896;    // [32][68]
    float* kvb  = sm + 35072;    // 2 x 8704
    float* mks  = sm + 52480;    // [1024]
    float* invs = sm + 53504;    // [32]

    const int q0 = blockIdx.x * 32;
    const int h  = blockIdx.y;
    const int b  = blockIdx.z;
    const int bh = b * Hx + h;
    const int t  = threadIdx.x;
    const int warp = t >> 5, lane = t & 31;
    const int r = lane >> 2, cq = lane & 3;
    const int wm = warp >> 3;       // scores: 2(M) x 8(N)
    const int wn = warp & 7;
    const float* base = qkv + (size_t)b * Sx * TDx;
    const float* kTb = kT + (size_t)bh * Sx * HDx;
    const float* vTb = vT + (size_t)bh * HDx * Sx;

    auto stageK = [&](int buf, int j0) {
        float* dstb = kvb + buf * 8704;
        #pragma unroll
        for (int i = 0; i < 4; i++) {
            int id = t + i * 512;
            int jj = id >> 4, c = id & 15;
            unsigned d = (unsigned)__cvta_generic_to_shared(&dstb[jj * 68 + c * 4]);
            CP16(d, &kTb[(size_t)(j0 + jj) * HDx + c * 4]);
        }
    };
    // V staged by PV half only (threads 256..511)
    auto stageV = [&](int buf, int j0) {
        float* dstb = kvb + buf * 8704;
        int t2 = t - 256;
        #pragma unroll
        for (int i = 0; i < 8; i++) {
            int id = t2 + i * 256;
            int dd = id >> 5, c = id & 31;
            unsigned d = (unsigned)__cvta_generic_to_shared(&dstb[dd * 132 + c * 4]);
            CP16(d, &vTb[(size_t)dd * Sx + j0 + c * 4]);
        }
    };

    if (t < 256) *(float4*)&mks[4 * t] = *(const float4*)&mask[b * Sx + 4 * t];
    #pragma unroll
    for (int i = 0; i < 4; i++) {
        int id = t + i * 512;
        int rr = id >> 6, d = id & 63;
        qs[rr * 68 + d] = tf32f(base[(size_t)(q0 + rr) * TDx + h * HDx + d]);
    }

    const int ntile = (q0 + 31) / 128 + 1;
    const int Ccols = ntile * 128;

    stageK(0, 0);
    CP_COMMIT();
    __syncthreads();

    // ---- scores ----
    for (int jt = 0; jt < ntile; jt++) {
        const int j0 = jt * 128;
        if (jt + 1 < ntile) { stageK((jt + 1) & 1, (jt + 1) * 128); CP_COMMIT(); CP_WAIT1(); }
        else                { CP_WAIT0(); }
        __syncthreads();
        const float* kvt = kvb + (jt & 1) * 8704;

        float c[2][4];
        #pragma unroll
        for (int i = 0; i < 2; i++)
            #pragma unroll
            for (int j = 0; j < 4; j++) c[i][j] = 0.f;

        #pragma unroll
        for (int ks = 0; ks < 8; ks++) {
            const int kb = ks * 8;
            unsigned a[4];
            const float* ap0 = &qs[(wm * 16 + r) * 68 + kb + cq];
            const float* ap1 = ap0 + 8 * 68;
            a[0] = __float_as_uint(ap0[0]);
            a[1] = __float_as_uint(ap1[0]);
            a[2] = __float_as_uint(ap0[4]);
            a[3] = __float_as_uint(ap1[4]);
            #pragma unroll
            for (int nn = 0; nn < 2; nn++) {
                const float* bp = &kvt[(wn * 16 + nn * 8 + r) * 68 + kb + cq];
                unsigned bf[2] = {__float_as_uint(bp[0]), __float_as_uint(bp[4])};
                mma_tf32(c[nn], a, bf);
            }
        }

        const int qa = q0 + wm * 16 + r;
        const int qb = qa + 8;
        #pragma unroll
        for (int nn = 0; nn < 2; nn++) {
            int jl = wn * 16 + nn * 8 + 2 * cq;
            int jg = j0 + jl;
            float mk0 = mks[jg], mk1 = mks[jg + 1];
            float* s0 = &sc[(wm * 16 + r) * SCS + jg];
            float* s1 = &sc[(wm * 16 + r + 8) * SCS + jg];
            s0[0] = (jg     <= qa) ? tf32f(expapx(fmaf(c[nn][0], 0.125f, mk0))) : 0.f;
            s0[1] = (jg + 1 <= qa) ? tf32f(expapx(fmaf(c[nn][1], 0.125f, mk1))) : 0.f;
            s1[0] = (jg     <= qb) ? tf32f(expapx(fmaf(c[nn][2], 0.125f, mk0))) : 0.f;
            s1[1] = (jg + 1 <= qb) ? tf32f(expapx(fmaf(c[nn][3], 0.125f, mk1))) : 0.f;
        }
        __syncthreads();
    }
    // sc complete for all warps here.

    float oc[2][4];
    #pragma unroll
    for (int i = 0; i < 2; i++)
        #pragma unroll
        for (int j = 0; j < 4; j++) oc[i][j] = 0.f;

    if (warp < 8) {
        // ---- w-store half: rowsum + normalized w store + zero fill ----
        #pragma unroll
        for (int rr = 0; rr < 4; rr++) {
            int row = warp * 4 + rr;
            int q = q0 + row;
            float s = 0.f;
            for (int j4 = lane * 4; j4 < Ccols; j4 += 128) {
                float4 v = *(float4*)&sc[row * SCS + j4];
                s += v.x + v.y + v.z + v.w;
            }
            #pragma unroll
            for (int o = 16; o > 0; o >>= 1) s += __shfl_xor_sync(0xffffffffu, s, o);
            float inv = 1.f / s;
            if (lane == 0) invs[row] = inv;
            size_t wb = ((size_t)(bh * Sx + q)) * Sx;
            for (int j4 = lane * 4; j4 < Ccols; j4 += 128) {
                float4 v = *(float4*)&sc[row * SCS + j4];
                float4 o4 = {v.x * inv, v.y * inv, v.z * inv, v.w * inv};
                *(float4*)&w_out[wb + j4] = o4;
            }
            float4 z = {0.f, 0.f, 0.f, 0.f};
            for (int j4 = Ccols + lane * 4; j4 < Sx; j4 += 128)
                *(float4*)&w_out[wb + j4] = z;
        }
    } else {
        // ---- PV half: 8 warps, 2(M) x 4(N of 16 cols) ----
        const int pwm = (warp - 8) >> 2;
        const int pwn = (warp - 8) & 3;

        stageV(0, 0);
        CP_COMMIT();

        for (int jt = 0; jt < ntile; jt++) {
            const int j0 = jt * 128;
            if (jt + 1 < ntile) { stageV((jt + 1) & 1, (jt + 1) * 128); CP_COMMIT(); CP_WAIT1(); }
            else                { CP_WAIT0(); }
            BARP();
            const float* kvt = kvb + (jt & 1) * 8704;

            #pragma unroll
            for (int ks = 0; ks < 16; ks++) {
                const int kb = ks * 8;
                unsigned a[4];
                const float* ap0 = &sc[(pwm * 16 + r) * SCS + j0 + kb + cq];
                const float* ap1 = ap0 + 8 * SCS;
                a[0] = __float_as_uint(ap0[0]);
                a[1] = __float_as_uint(ap1[0]);
                a[2] = __float_as_uint(ap0[4]);
                a[3] = __float_as_uint(ap1[4]);
                #pragma unroll
                for (int nn = 0; nn < 2; nn++) {
                    const float* bp = &kvt[(pwn * 16 + nn * 8 + r) * 132 + kb + cq];
                    unsigned bf[2] = {__float_as_uint(bp[0]), __float_as_uint(bp[4])};
                    mma_tf32(oc[nn], a, bf);
                }
            }
            BARP();
        }
    }
    __syncthreads();   // invs ready, PV done

    if (warp >= 8) {
        const int pwm = (warp - 8) >> 2;
        const int pwn = (warp - 8) & 3;
        int row_a = pwm * 16 + r, row_b = row_a + 8;
        float ia = invs[row_a], ib = invs[row_b];
        #pragma unroll
        for (int nn = 0; nn < 2; nn++) {
            int d = pwn * 16 + nn * 8 + 2 * cq;
            size_t ra = ((size_t)(b * Sx + q0 + row_a)) * Dx + h * HDx + d;
            size_t rb = ((size_t)(b * Sx + q0 + row_b)) * Dx + h * HDx + d;
            float2 v0 = {tf32f(oc[nn][0] * ia), tf32f(oc[nn][1] * ia)};
            float2 v1 = {tf32f(oc[nn][2] * ib), tf32f(oc[nn][3] * ib)};
            *(float2*)&aout[ra] = v0;
            *(float2*)&aout[rb] = v1;
        }
    }
}

// ---------------------------------------------------------------------------
extern "C" void kernel_launch(void* const* d_in, const int* in_sizes, int n_in,
                              void* d_out, int out_size) {
    const float* x      = (const float*)d_in[0];
    const float* mask   = (const float*)d_in[1];
    const float* w_attn = (const float*)d_in[2];
    const float* b_attn = (const float*)d_in[3];
    const float* w_proj = (const float*)d_in[4];
    const float* b_proj = (const float*)d_in[5];

    float* out_a = (float*)d_out;
    float* out_w = (float*)d_out + (size_t)Bx * Sx * Dx;

    float *qkv, *aout, *xr, *war, *wpr, *kT, *vT;
    cudaGetSymbolAddress((void**)&qkv,  g_qkv);
    cudaGetSymbolAddress((void**)&aout, g_aout);
    cudaGetSymbolAddress((void**)&xr,   g_xr);
    cudaGetSymbolAddress((void**)&war,  g_war);
    cudaGetSymbolAddress((void**)&wpr,  g_wpr);
    cudaGetSymbolAddress((void**)&kT,   g_kT);
    cudaGetSymbolAddress((void**)&vT,   g_vT);

    static const int ATTN_SMEM = 53536 * 4;   // 214144 B
    cudaFuncSetAttribute(attn_mma, cudaFuncAttributeMaxDynamicSharedMemorySize, ATTN_SMEM);
    cudaFuncSetAttribute(gemm_mma, cudaFuncAttributeMaxDynamicSharedMemorySize, GEMM_SMEM);

    {
        int n;
        n = Bx * Sx * Dx / 4;  round_tf32<<<(n + 255) / 256, 256>>>(x, xr, n);
        n = Dx * TDx / 4;      round_tf32<<<(n + 255) / 256, 256>>>(w_attn, war, n);
        n = Dx * Dx / 4;       round_tf32<<<(n + 255) / 256, 256>>>(w_proj, wpr, n);
    }
    {
        dim3 grid(TDx / 128, (Bx * Sx) / 128);
        gemm_mma<<<grid, 256, GEMM_SMEM>>>(xr, war, b_attn, qkv, Bx * Sx, TDx, Dx);
    }
    {
        prep_kT<<<(Bx * Hx * Sx * 16) / 256, 256>>>(qkv, kT);
        dim3 gv(Sx / 64, Bx * Hx);
        prep_vT<<<gv, 256>>>(qkv, vT);
    }
    {
        dim3 grid(Sx / 32, Hx, Bx);
        attn_mma<<<grid, 512, ATTN_SMEM>>>(qkv, kT, vT, mask, out_w, aout);
    }
    {
        dim3 grid(Dx / 128, (Bx * Sx) / 128);
        gemm_mma<<<grid, 256, GEMM_SMEM>>>(aout, wpr, b_proj, out_a, Bx * Sx, Dx, Dx);
    }
}

// round 12
// speedup vs baseline: 1.5638x; 1.0629x over previous
#include <cuda_runtime.h>
#include <cuda.h>
#include <cuda_bf16.h>
#include <cstdint>
#include <math.h>

#define Bx 4
#define Sx 1024
#define Dx 1024
#define Hx 16
#define HDx 64
#define TDx 3072
#define SCS 1028   // scores smem row stride (== 4 mod 32 -> conflict-free frags)

__device__ float g_qkv[Bx * Sx * TDx];
__device__ float g_aout[Bx * Sx * Dx];
__device__ float g_xr[Bx * Sx * Dx];
__device__ float g_war[Dx * TDx];
__device__ float g_wpr[Dx * Dx];
__device__ float g_kT[Bx * Hx * Sx * HDx];   // [bh][j][d] tf32 K
__device__ float g_vT[Bx * Hx * HDx * Sx];   // [bh][d][j] tf32 V^T

// ---------------------------------------------------------------------------
__device__ __forceinline__ unsigned f2tf32(float f) {
    unsigned r;
    asm("cvt.rna.tf32.f32 %0, %1;" : "=r"(r) : "f"(f));
    return r;
}
__device__ __forceinline__ float tf32f(float f) { return __uint_as_float(f2tf32(f)); }

__device__ __forceinline__ void mma_tf32(float c[4], const unsigned a[4], const unsigned b[2]) {
    asm volatile("mma.sync.aligned.m16n8k8.row.col.f32.tf32.tf32.f32 "
        "{%0,%1,%2,%3}, {%4,%5,%6,%7}, {%8,%9}, {%0,%1,%2,%3};"
        : "+f"(c[0]), "+f"(c[1]), "+f"(c[2]), "+f"(c[3])
        : "r"(a[0]), "r"(a[1]), "r"(a[2]), "r"(a[3]), "r"(b[0]), "r"(b[1]));
}

__device__ __forceinline__ float expapx(float x) {
    float y = fmaxf(x * 1.4426950408889634f, -80.f);
    float t = y + 12582912.f;
    int   n = __float_as_int(t) - 0x4b400000;
    float f = y - (t - 12582912.f);
    float p = 1.3333558146428443e-3f;
    p = fmaf(p, f, 9.618129842118066e-3f);
    p = fmaf(p, f, 5.550410866482158e-2f);
    p = fmaf(p, f, 2.402265069591007e-1f);
    p = fmaf(p, f, 6.931471805599453e-1f);
    p = fmaf(p, f, 1.0f);
    return __int_as_float(__float_as_int(p) + (n << 23));
}

#define CP16(dst, src) asm volatile("cp.async.cg.shared.global [%0], [%1], 16;" :: "r"(dst), "l"(src))
#define CP_COMMIT()    asm volatile("cp.async.commit_group;")
#define CP_WAIT1()     asm volatile("cp.async.wait_group 1;")
#define CP_WAIT0()     asm volatile("cp.async.wait_group 0;")
#define BARP()         asm volatile("bar.sync 1, 256;" ::: "memory")

// ---------------------------------------------------------------------------
__global__ void round_tf32(const float* __restrict__ in, float* __restrict__ out, int n4) {
    int i = blockIdx.x * blockDim.x + threadIdx.x;
    if (i < n4) {
        float4 v = ((const float4*)in)[i];
        uint4 o;
        o.x = f2tf32(v.x); o.y = f2tf32(v.y); o.z = f2tf32(v.z); o.w = f2tf32(v.w);
        ((uint4*)out)[i] = o;
    }
}

// kT[bh][j][d] = tf32(K)
__global__ void prep_kT(const float* __restrict__ qkv, float* __restrict__ kT) {
    int i = blockIdx.x * 256 + threadIdx.x;
    int c = i & 15, j = (i >> 4) & 1023, bh = i >> 14;
    int b = bh >> 4, h = bh & 15;
    float4 v = *(const float4*)&qkv[((size_t)(b * Sx + j)) * TDx + Dx + h * HDx + c * 4];
    uint4 o = {f2tf32(v.x), f2tf32(v.y), f2tf32(v.z), f2tf32(v.w)};
    *(uint4*)&kT[(size_t)i * 4] = o;
}

// vT[bh][d][j] = tf32(V)
__global__ void prep_vT(const float* __restrict__ qkv, float* __restrict__ vT) {
    __shared__ float tile[64][68];
    int bh = blockIdx.y, j0 = blockIdx.x * 64;
    int b = bh >> 4, h = bh & 15;
    int t = threadIdx.x;
    #pragma unroll
    for (int i = 0; i < 4; i++) {
        int id = t + i * 256;
        int jj = id >> 4, c = id & 15;
        float4 v = *(const float4*)&qkv[((size_t)(b * Sx + j0 + jj)) * TDx + 2 * Dx + h * HDx + c * 4];
        tile[jj][c * 4 + 0] = tf32f(v.x);
        tile[jj][c * 4 + 1] = tf32f(v.y);
        tile[jj][c * 4 + 2] = tf32f(v.z);
        tile[jj][c * 4 + 3] = tf32f(v.w);
    }
    __syncthreads();
    #pragma unroll
    for (int i = 0; i < 4; i++) {
        int id = t + i * 256;
        int d = id >> 4, c = id & 15;
        float4 o = {tile[c * 4 + 0][d], tile[c * 4 + 1][d], tile[c * 4 + 2][d], tile[c * 4 + 3][d]};
        *(float4*)&vT[((size_t)(bh * HDx + d)) * Sx + j0 + c * 4] = o;
    }
}

// ---------------------------------------------------------------------------
// tf32 GEMM, k-tile 32 (4 ks steps, 64 mma per barrier), 3-stage cp.async.
// A smem [128][36] (stride 36: conflict-free frags), B smem [32][136].
// Stage = 35840 B, 3 stages = 107520 B. 2 CTAs/SM (reg-limited, as before).
// ---------------------------------------------------------------------------
#define GEMM_SMEM 107520
#define ASTG 4608   // A stage floats: 128*36
#define BSTG 4352   // B stage floats: 32*136
__global__ __launch_bounds__(256) void gemm_mma(const float* __restrict__ A,
                                                const float* __restrict__ B,
                                                const float* __restrict__ bias,
                                                float* __restrict__ C,
                                                int M, int N, int K) {
    extern __shared__ float gsm[];
    float* Asb = gsm;                 // 3 stages of [128][36]
    float* Bsb = gsm + 3 * ASTG;      // 3 stages of [32][136]

    const int t = threadIdx.x;
    const int warp = t >> 5, lane = t & 31;
    const int wm = warp >> 2, wn = warp & 3;
    const int r = lane >> 2, cq = lane & 3;
    const int row0 = blockIdx.y * 128, col0 = blockIdx.x * 128;

    float acc[4][4][4];
    #pragma unroll
    for (int i = 0; i < 4; i++)
        #pragma unroll
        for (int j = 0; j < 4; j++)
            #pragma unroll
            for (int k = 0; k < 4; k++) acc[i][j][k] = 0.f;

    // per-stage: A = 128 rows x 8 chunks (1024), B = 32 rows x 32 chunks (1024)
    auto loadG = [&](int st, int k0) {
        float* As = Asb + st * ASTG;
        float* Bs = Bsb + st * BSTG;
        #pragma unroll
        for (int i = 0; i < 4; i++) {
            int id = t + i * 256;
            int am = id >> 3, ac = id & 7;
            unsigned da = (unsigned)__cvta_generic_to_shared(&As[am * 36 + ac * 4]);
            CP16(da, &A[(size_t)(row0 + am) * K + k0 + ac * 4]);
            int bk = id >> 5, bn = id & 31;
            unsigned db = (unsigned)__cvta_generic_to_shared(&Bs[bk * 136 + bn * 4]);
            CP16(db, &B[(size_t)(k0 + bk) * N + col0 + bn * 4]);
        }
    };

    loadG(0, 0);  CP_COMMIT();
    loadG(1, 32); CP_COMMIT();

    const int NT = K / 32;
    int st = 0;
    for (int kt = 0; kt < NT; kt++) {
        if (kt + 1 < NT) CP_WAIT1(); else CP_WAIT0();
        __syncthreads();
        if (kt + 2 < NT) {
            int st2 = st + 2; if (st2 >= 3) st2 -= 3;
            loadG(st2, (kt + 2) * 32);
            CP_COMMIT();
        }
        const float* As = Asb + st * ASTG;
        const float* Bs = Bsb + st * BSTG;

        #pragma unroll
        for (int ks = 0; ks < 4; ks++) {
            const int kb = ks * 8;
            unsigned a[4][4], b[4][2];
            #pragma unroll
            for (int mm = 0; mm < 4; mm++) {
                const float* ap0 = &As[(wm * 64 + mm * 16 + r) * 36 + kb + cq];
                const float* ap1 = ap0 + 8 * 36;
                a[mm][0] = __float_as_uint(ap0[0]);
                a[mm][1] = __float_as_uint(ap1[0]);
                a[mm][2] = __float_as_uint(ap0[4]);
                a[mm][3] = __float_as_uint(ap1[4]);
            }
            #pragma unroll
            for (int nn = 0; nn < 4; nn++) {
                const float* bp = &Bs[(kb + cq) * 136 + wn * 32 + nn * 8 + r];
                b[nn][0] = __float_as_uint(bp[0]);
                b[nn][1] = __float_as_uint(bp[4 * 136]);
            }
            #pragma unroll
            for (int mm = 0; mm < 4; mm++)
                #pragma unroll
                for (int nn = 0; nn < 4; nn++)
                    mma_tf32(acc[mm][nn], a[mm], b[nn]);
        }
        if (++st == 3) st = 0;
    }

    #pragma unroll
    for (int mm = 0; mm < 4; mm++) {
        int r0 = row0 + wm * 64 + mm * 16 + r;
        #pragma unroll
        for (int nn = 0; nn < 4; nn++) {
            int c0 = col0 + wn * 32 + nn * 8 + 2 * cq;
            float2 bv = *(const float2*)&bias[c0];
            float2 o0 = {acc[mm][nn][0] + bv.x, acc[mm][nn][1] + bv.y};
            float2 o1 = {acc[mm][nn][2] + bv.x, acc[mm][nn][3] + bv.y};
            *(float2*)&C[(size_t)r0 * N + c0] = o0;
            *(float2*)&C[(size_t)(r0 + 8) * N + c0] = o1;
        }
    }
}

// ---------------------------------------------------------------------------
// Tensor-core attention, 512 threads (unchanged from R11): scores all tiles,
// then warps 0-7 rowsum+w-store overlapped with warps 8-15 PV mma.
// ---------------------------------------------------------------------------
__global__ __launch_bounds__(512) void attn_mma(const float* __restrict__ qkv,
                                                const float* __restrict__ kT,
                                                const float* __restrict__ vT,
                                                const float* __restrict__ mask,
                                                float* __restrict__ w_out,
                                                float* __restrict__ aout) {
    extern __shared__ float sm[];
    float* sc   = sm;            // [32][SCS]
    float* qs   = sm + 32896;    // [32][68]
    float* kvb  = sm + 35072;    // 2 x 8704
    float* mks  = sm + 52480;    // [1024]
    float* invs = sm + 53504;    // [32]

    const int q0 = blockIdx.x * 32;
    const int h  = blockIdx.y;
    const int b  = blockIdx.z;
    const int bh = b * Hx + h;
    const int t  = threadIdx.x;
    const int warp = t >> 5, lane = t & 31;
    const int r = lane >> 2, cq = lane & 3;
    const int wm = warp >> 3;       // scores: 2(M) x 8(N)
    const int wn = warp & 7;
    const float* base = qkv + (size_t)b * Sx * TDx;
    const float* kTb = kT + (size_t)bh * Sx * HDx;
    const float* vTb = vT + (size_t)bh * HDx * Sx;

    auto stageK = [&](int buf, int j0) {
        float* dstb = kvb + buf * 8704;
        #pragma unroll
        for (int i = 0; i < 4; i++) {
            int id = t + i * 512;
            int jj = id >> 4, c = id & 15;
            unsigned d = (unsigned)__cvta_generic_to_shared(&dstb[jj * 68 + c * 4]);
            CP16(d, &kTb[(size_t)(j0 + jj) * HDx + c * 4]);
        }
    };
    // V staged by PV half only (threads 256..511)
    auto stageV = [&](int buf, int j0) {
        float* dstb = kvb + buf * 8704;
        int t2 = t - 256;
        #pragma unroll
        for (int i = 0; i < 8; i++) {
            int id = t2 + i * 256;
            int dd = id >> 5, c = id & 31;
            unsigned d = (unsigned)__cvta_generic_to_shared(&dstb[dd * 132 + c * 4]);
            CP16(d, &vTb[(size_t)dd * Sx + j0 + c * 4]);
        }
    };

    if (t < 256) *(float4*)&mks[4 * t] = *(const float4*)&mask[b * Sx + 4 * t];
    #pragma unroll
    for (int i = 0; i < 4; i++) {
        int id = t + i * 512;
        int rr = id >> 6, d = id & 63;
        qs[rr * 68 + d] = tf32f(base[(size_t)(q0 + rr) * TDx + h * HDx + d]);
    }

    const int ntile = (q0 + 31) / 128 + 1;
    const int Ccols = ntile * 128;

    stageK(0, 0);
    CP_COMMIT();
    __syncthreads();

    // ---- scores ----
    for (int jt = 0; jt < ntile; jt++) {
        const int j0 = jt * 128;
        if (jt + 1 < ntile) { stageK((jt + 1) & 1, (jt + 1) * 128); CP_COMMIT(); CP_WAIT1(); }
        else                { CP_WAIT0(); }
        __syncthreads();
        const float* kvt = kvb + (jt & 1) * 8704;

        float c[2][4];
        #pragma unroll
        for (int i = 0; i < 2; i++)
            #pragma unroll
            for (int j = 0; j < 4; j++) c[i][j] = 0.f;

        #pragma unroll
        for (int ks = 0; ks < 8; ks++) {
            const int kb = ks * 8;
            unsigned a[4];
            const float* ap0 = &qs[(wm * 16 + r) * 68 + kb + cq];
            const float* ap1 = ap0 + 8 * 68;
            a[0] = __float_as_uint(ap0[0]);
            a[1] = __float_as_uint(ap1[0]);
            a[2] = __float_as_uint(ap0[4]);
            a[3] = __float_as_uint(ap1[4]);
            #pragma unroll
            for (int nn = 0; nn < 2; nn++) {
                const float* bp = &kvt[(wn * 16 + nn * 8 + r) * 68 + kb + cq];
                unsigned bf[2] = {__float_as_uint(bp[0]), __float_as_uint(bp[4])};
                mma_tf32(c[nn], a, bf);
            }
        }

        const int qa = q0 + wm * 16 + r;
        const int qb = qa + 8;
        #pragma unroll
        for (int nn = 0; nn < 2; nn++) {
            int jl = wn * 16 + nn * 8 + 2 * cq;
            int jg = j0 + jl;
            float mk0 = mks[jg], mk1 = mks[jg + 1];
            float* s0 = &sc[(wm * 16 + r) * SCS + jg];
            float* s1 = &sc[(wm * 16 + r + 8) * SCS + jg];
            s0[0] = (jg     <= qa) ? tf32f(expapx(fmaf(c[nn][0], 0.125f, mk0))) : 0.f;
            s0[1] = (jg + 1 <= qa) ? tf32f(expapx(fmaf(c[nn][1], 0.125f, mk1))) : 0.f;
            s1[0] = (jg     <= qb) ? tf32f(expapx(fmaf(c[nn][2], 0.125f, mk0))) : 0.f;
            s1[1] = (jg + 1 <= qb) ? tf32f(expapx(fmaf(c[nn][3], 0.125f, mk1))) : 0.f;
        }
        __syncthreads();
    }
    // sc complete for all warps here.

    float oc[2][4];
    #pragma unroll
    for (int i = 0; i < 2; i++)
        #pragma unroll
        for (int j = 0; j < 4; j++) oc[i][j] = 0.f;

    if (warp < 8) {
        // ---- w-store half: rowsum + normalized w store + zero fill ----
        #pragma unroll
        for (int rr = 0; rr < 4; rr++) {
            int row = warp * 4 + rr;
            int q = q0 + row;
            float s = 0.f;
            for (int j4 = lane * 4; j4 < Ccols; j4 += 128) {
                float4 v = *(float4*)&sc[row * SCS + j4];
                s += v.x + v.y + v.z + v.w;
            }
            #pragma unroll
            for (int o = 16; o > 0; o >>= 1) s += __shfl_xor_sync(0xffffffffu, s, o);
            float inv = 1.f / s;
            if (lane == 0) invs[row] = inv;
            size_t wb = ((size_t)(bh * Sx + q)) * Sx;
            for (int j4 = lane * 4; j4 < Ccols; j4 += 128) {
                float4 v = *(float4*)&sc[row * SCS + j4];
                float4 o4 = {v.x * inv, v.y * inv, v.z * inv, v.w * inv};
                *(float4*)&w_out[wb + j4] = o4;
            }
            float4 z = {0.f, 0.f, 0.f, 0.f};
            for (int j4 = Ccols + lane * 4; j4 < Sx; j4 += 128)
                *(float4*)&w_out[wb + j4] = z;
        }
    } else {
        // ---- PV half: 8 warps, 2(M) x 4(N of 16 cols) ----
        const int pwm = (warp - 8) >> 2;
        const int pwn = (warp - 8) & 3;

        stageV(0, 0);
        CP_COMMIT();

        for (int jt = 0; jt < ntile; jt++) {
            const int j0 = jt * 128;
            if (jt + 1 < ntile) { stageV((jt + 1) & 1, (jt + 1) * 128); CP_COMMIT(); CP_WAIT1(); }
            else                { CP_WAIT0(); }
            BARP();
            const float* kvt = kvb + (jt & 1) * 8704;

            #pragma unroll
            for (int ks = 0; ks < 16; ks++) {
                const int kb = ks * 8;
                unsigned a[4];
                const float* ap0 = &sc[(pwm * 16 + r) * SCS + j0 + kb + cq];
                const float* ap1 = ap0 + 8 * SCS;
                a[0] = __float_as_uint(ap0[0]);
                a[1] = __float_as_uint(ap1[0]);
                a[2] = __float_as_uint(ap0[4]);
                a[3] = __float_as_uint(ap1[4]);
                #pragma unroll
                for (int nn = 0; nn < 2; nn++) {
                    const float* bp = &kvt[(pwn * 16 + nn * 8 + r) * 132 + kb + cq];
                    unsigned bf[2] = {__float_as_uint(bp[0]), __float_as_uint(bp[4])};
                    mma_tf32(oc[nn], a, bf);
                }
            }
            BARP();
        }
    }
    __syncthreads();   // invs ready, PV done

    if (warp >= 8) {
        const int pwm = (warp - 8) >> 2;
        const int pwn = (warp - 8) & 3;
        int row_a = pwm * 16 + r, row_b = row_a + 8;
        float ia = invs[row_a], ib = invs[row_b];
        #pragma unroll
        for (int nn = 0; nn < 2; nn++) {
            int d = pwn * 16 + nn * 8 + 2 * cq;
            size_t ra = ((size_t)(b * Sx + q0 + row_a)) * Dx + h * HDx + d;
            size_t rb = ((size_t)(b * Sx + q0 + row_b)) * Dx + h * HDx + d;
            float2 v0 = {tf32f(oc[nn][0] * ia), tf32f(oc[nn][1] * ia)};
            float2 v1 = {tf32f(oc[nn][2] * ib), tf32f(oc[nn][3] * ib)};
            *(float2*)&aout[ra] = v0;
            *(float2*)&aout[rb] = v1;
        }
    }
}

// ---------------------------------------------------------------------------
extern "C" void kernel_launch(void* const* d_in, const int* in_sizes, int n_in,
                              void* d_out, int out_size) {
    const float* x      = (const float*)d_in[0];
    const float* mask   = (const float*)d_in[1];
    const float* w_attn = (const float*)d_in[2];
    const float* b_attn = (const float*)d_in[3];
    const float* w_proj = (const float*)d_in[4];
    const float* b_proj = (const float*)d_in[5];

    float* out_a = (float*)d_out;
    float* out_w = (float*)d_out + (size_t)Bx * Sx * Dx;

    float *qkv, *aout, *xr, *war, *wpr, *kT, *vT;
    cudaGetSymbolAddress((void**)&qkv,  g_qkv);
    cudaGetSymbolAddress((void**)&aout, g_aout);
    cudaGetSymbolAddress((void**)&xr,   g_xr);
    cudaGetSymbolAddress((void**)&war,  g_war);
    cudaGetSymbolAddress((void**)&wpr,  g_wpr);
    cudaGetSymbolAddress((void**)&kT,   g_kT);
    cudaGetSymbolAddress((void**)&vT,   g_vT);

    static const int ATTN_SMEM = 53536 * 4;   // 214144 B
    cudaFuncSetAttribute(attn_mma, cudaFuncAttributeMaxDynamicSharedMemorySize, ATTN_SMEM);
    cudaFuncSetAttribute(gemm_mma, cudaFuncAttributeMaxDynamicSharedMemorySize, GEMM_SMEM);

    {
        int n;
        n = Bx * Sx * Dx / 4;  round_tf32<<<(n + 255) / 256, 256>>>(x, xr, n);
        n = Dx * TDx / 4;      round_tf32<<<(n + 255) / 256, 256>>>(w_attn, war, n);
        n = Dx * Dx / 4;       round_tf32<<<(n + 255) / 256, 256>>>(w_proj, wpr, n);
    }
    {
        dim3 grid(TDx / 128, (Bx * Sx) / 128);
        gemm_mma<<<grid, 256, GEMM_SMEM>>>(xr, war, b_attn, qkv, Bx * Sx, TDx, Dx);
    }
    {
        prep_kT<<<(Bx * Hx * Sx * 16) / 256, 256>>>(qkv, kT);
        dim3 gv(Sx / 64, Bx * Hx);
        prep_vT<<<gv, 256>>>(qkv, vT);
    }
    {
        dim3 grid(Sx / 32, Hx, Bx);
        attn_mma<<<grid, 512, ATTN_SMEM>>>(qkv, kT, vT, mask, out_w, aout);
    }
    {
        dim3 grid(Dx / 128, (Bx * Sx) / 128);
        gemm_mma<<<grid, 256, GEMM_SMEM>>>(aout, wpr, b_proj, out_a, Bx * Sx, Dx, Dx);
    }
}

// round 13
// speedup vs baseline: 1.6447x; 1.0517x over previous
#include <cuda_runtime.h>
#include <cuda.h>
#include <cuda_bf16.h>
#include <cstdint>
#include <math.h>

#define Bx 4
#define Sx 1024
#define Dx 1024
#define Hx 16
#define HDx 64
#define TDx 3072
#define SCS 1028   // scores smem row stride (== 4 mod 32 -> conflict-free frags)

__device__ float g_qkv[Bx * Sx * TDx];
__device__ float g_aout[Bx * Sx * Dx];
__device__ float g_xr[Bx * Sx * Dx];
__device__ float g_war[Dx * TDx];
__device__ float g_wpr[Dx * Dx];
__device__ float g_kT[Bx * Hx * Sx * HDx];   // [bh][j][d] tf32 K
__device__ float g_vT[Bx * Hx * HDx * Sx];   // [bh][d][j] tf32 V^T

// ---------------------------------------------------------------------------
__device__ __forceinline__ unsigned f2tf32(float f) {
    unsigned r;
    asm("cvt.rna.tf32.f32 %0, %1;" : "=r"(r) : "f"(f));
    return r;
}
__device__ __forceinline__ float tf32f(float f) { return __uint_as_float(f2tf32(f)); }

__device__ __forceinline__ void mma_tf32(float c[4], const unsigned a[4], const unsigned b[2]) {
    asm volatile("mma.sync.aligned.m16n8k8.row.col.f32.tf32.tf32.f32 "
        "{%0,%1,%2,%3}, {%4,%5,%6,%7}, {%8,%9}, {%0,%1,%2,%3};"
        : "+f"(c[0]), "+f"(c[1]), "+f"(c[2]), "+f"(c[3])
        : "r"(a[0]), "r"(a[1]), "r"(a[2]), "r"(a[3]), "r"(b[0]), "r"(b[1]));
}

__device__ __forceinline__ float expapx(float x) {
    float y = fmaxf(x * 1.4426950408889634f, -80.f);
    float t = y + 12582912.f;
    int   n = __float_as_int(t) - 0x4b400000;
    float f = y - (t - 12582912.f);
    float p = 1.3333558146428443e-3f;
    p = fmaf(p, f, 9.618129842118066e-3f);
    p = fmaf(p, f, 5.550410866482158e-2f);
    p = fmaf(p, f, 2.402265069591007e-1f);
    p = fmaf(p, f, 6.931471805599453e-1f);
    p = fmaf(p, f, 1.0f);
    return __int_as_float(__float_as_int(p) + (n << 23));
}

#define CP16(dst, src) asm volatile("cp.async.cg.shared.global [%0], [%1], 16;" :: "r"(dst), "l"(src))
#define CP_COMMIT()    asm volatile("cp.async.commit_group;")
#define CP_WAIT1()     asm volatile("cp.async.wait_group 1;")
#define CP_WAIT0()     asm volatile("cp.async.wait_group 0;")
#define BARP()         asm volatile("bar.sync 1, 256;" ::: "memory")

// ---------------------------------------------------------------------------
__global__ void round_tf32(const float* __restrict__ in, float* __restrict__ out, int n4) {
    int i = blockIdx.x * blockDim.x + threadIdx.x;
    if (i < n4) {
        float4 v = ((const float4*)in)[i];
        uint4 o;
        o.x = f2tf32(v.x); o.y = f2tf32(v.y); o.z = f2tf32(v.z); o.w = f2tf32(v.w);
        ((uint4*)out)[i] = o;
    }
}

// kT[bh][j][d] = tf32(K)
__global__ void prep_kT(const float* __restrict__ qkv, float* __restrict__ kT) {
    int i = blockIdx.x * 256 + threadIdx.x;
    int c = i & 15, j = (i >> 4) & 1023, bh = i >> 14;
    int b = bh >> 4, h = bh & 15;
    float4 v = *(const float4*)&qkv[((size_t)(b * Sx + j)) * TDx + Dx + h * HDx + c * 4];
    uint4 o = {f2tf32(v.x), f2tf32(v.y), f2tf32(v.z), f2tf32(v.w)};
    *(uint4*)&kT[(size_t)i * 4] = o;
}

// vT[bh][d][j] = tf32(V)
__global__ void prep_vT(const float* __restrict__ qkv, float* __restrict__ vT) {
    __shared__ float tile[64][68];
    int bh = blockIdx.y, j0 = blockIdx.x * 64;
    int b = bh >> 4, h = bh & 15;
    int t = threadIdx.x;
    #pragma unroll
    for (int i = 0; i < 4; i++) {
        int id = t + i * 256;
        int jj = id >> 4, c = id & 15;
        float4 v = *(const float4*)&qkv[((size_t)(b * Sx + j0 + jj)) * TDx + 2 * Dx + h * HDx + c * 4];
        tile[jj][c * 4 + 0] = tf32f(v.x);
        tile[jj][c * 4 + 1] = tf32f(v.y);
        tile[jj][c * 4 + 2] = tf32f(v.z);
        tile[jj][c * 4 + 3] = tf32f(v.w);
    }
    __syncthreads();
    #pragma unroll
    for (int i = 0; i < 4; i++) {
        int id = t + i * 256;
        int d = id >> 4, c = id & 15;
        float4 o = {tile[c * 4 + 0][d], tile[c * 4 + 1][d], tile[c * 4 + 2][d], tile[c * 4 + 3][d]};
        *(float4*)&vT[((size_t)(bh * HDx + d)) * Sx + j0 + c * 4] = o;
    }
}

// ---------------------------------------------------------------------------
// tf32 GEMM, k-tile 32 (4 ks steps, 64 mma per barrier), 3-stage cp.async.
// __launch_bounds__(256,2): cap regs at 128 so 2 CTAs/SM fit (smem 2x107520
// = 215KB <= 228KB carveout).
// ---------------------------------------------------------------------------
#define GEMM_SMEM 107520
#define ASTG 4608   // A stage floats: 128*36
#define BSTG 4352   // B stage floats: 32*136
__global__ __launch_bounds__(256, 2) void gemm_mma(const float* __restrict__ A,
                                                   const float* __restrict__ B,
                                                   const float* __restrict__ bias,
                                                   float* __restrict__ C,
                                                   int M, int N, int K) {
    extern __shared__ float gsm[];
    float* Asb = gsm;                 // 3 stages of [128][36]
    float* Bsb = gsm + 3 * ASTG;      // 3 stages of [32][136]

    const int t = threadIdx.x;
    const int warp = t >> 5, lane = t & 31;
    const int wm = warp >> 2, wn = warp & 3;
    const int r = lane >> 2, cq = lane & 3;
    const int row0 = blockIdx.y * 128, col0 = blockIdx.x * 128;

    float acc[4][4][4];
    #pragma unroll
    for (int i = 0; i < 4; i++)
        #pragma unroll
        for (int j = 0; j < 4; j++)
            #pragma unroll
            for (int k = 0; k < 4; k++) acc[i][j][k] = 0.f;

    // per-stage: A = 128 rows x 8 chunks (1024), B = 32 rows x 32 chunks (1024)
    auto loadG = [&](int st, int k0) {
        float* As = Asb + st * ASTG;
        float* Bs = Bsb + st * BSTG;
        #pragma unroll
        for (int i = 0; i < 4; i++) {
            int id = t + i * 256;
            int am = id >> 3, ac = id & 7;
            unsigned da = (unsigned)__cvta_generic_to_shared(&As[am * 36 + ac * 4]);
            CP16(da, &A[(size_t)(row0 + am) * K + k0 + ac * 4]);
            int bk = id >> 5, bn = id & 31;
            unsigned db = (unsigned)__cvta_generic_to_shared(&Bs[bk * 136 + bn * 4]);
            CP16(db, &B[(size_t)(k0 + bk) * N + col0 + bn * 4]);
        }
    };

    loadG(0, 0);  CP_COMMIT();
    loadG(1, 32); CP_COMMIT();

    const int NT = K / 32;
    int st = 0;
    for (int kt = 0; kt < NT; kt++) {
        if (kt + 1 < NT) CP_WAIT1(); else CP_WAIT0();
        __syncthreads();
        if (kt + 2 < NT) {
            int st2 = st + 2; if (st2 >= 3) st2 -= 3;
            loadG(st2, (kt + 2) * 32);
            CP_COMMIT();
        }
        const float* As = Asb + st * ASTG;
        const float* Bs = Bsb + st * BSTG;

        #pragma unroll
        for (int ks = 0; ks < 4; ks++) {
            const int kb = ks * 8;
            unsigned a[4][4], b[4][2];
            #pragma unroll
            for (int mm = 0; mm < 4; mm++) {
                const float* ap0 = &As[(wm * 64 + mm * 16 + r) * 36 + kb + cq];
                const float* ap1 = ap0 + 8 * 36;
                a[mm][0] = __float_as_uint(ap0[0]);
                a[mm][1] = __float_as_uint(ap1[0]);
                a[mm][2] = __float_as_uint(ap0[4]);
                a[mm][3] = __float_as_uint(ap1[4]);
            }
            #pragma unroll
            for (int nn = 0; nn < 4; nn++) {
                const float* bp = &Bs[(kb + cq) * 136 + wn * 32 + nn * 8 + r];
                b[nn][0] = __float_as_uint(bp[0]);
                b[nn][1] = __float_as_uint(bp[4 * 136]);
            }
            #pragma unroll
            for (int mm = 0; mm < 4; mm++)
                #pragma unroll
                for (int nn = 0; nn < 4; nn++)
                    mma_tf32(acc[mm][nn], a[mm], b[nn]);
        }
        if (++st == 3) st = 0;
    }

    #pragma unroll
    for (int mm = 0; mm < 4; mm++) {
        int r0 = row0 + wm * 64 + mm * 16 + r;
        #pragma unroll
        for (int nn = 0; nn < 4; nn++) {
            int c0 = col0 + wn * 32 + nn * 8 + 2 * cq;
            float2 bv = *(const float2*)&bias[c0];
            float2 o0 = {acc[mm][nn][0] + bv.x, acc[mm][nn][1] + bv.y};
            float2 o1 = {acc[mm][nn][2] + bv.x, acc[mm][nn][3] + bv.y};
            *(float2*)&C[(size_t)r0 * N + c0] = o0;
            *(float2*)&C[(size_t)(r0 + 8) * N + c0] = o1;
        }
    }
}

// ---------------------------------------------------------------------------
// Tensor-core attention, 512 threads (unchanged): scores all tiles,
// then warps 0-7 rowsum+w-store overlapped with warps 8-15 PV mma.
// ---------------------------------------------------------------------------
__global__ __launch_bounds__(512) void attn_mma(const float* __restrict__ qkv,
                                                const float* __restrict__ kT,
                                                const float* __restrict__ vT,
                                                const float* __restrict__ mask,
                                                float* __restrict__ w_out,
                                                float* __restrict__ aout) {
    extern __shared__ float sm[];
    float* sc   = sm;            // [32][SCS]
    float* qs   = sm + 32896;    // [32][68]
    float* kvb  = sm + 35072;    // 2 x 8704
    float* mks  = sm + 52480;    // [1024]
    float* invs = sm + 53504;    // [32]

    const int q0 = blockIdx.x * 32;
    const int h  = blockIdx.y;
    const int b  = blockIdx.z;
    const int bh = b * Hx + h;
    const int t  = threadIdx.x;
    const int warp = t >> 5, lane = t & 31;
    const int r = lane >> 2, cq = lane & 3;
    const int wm = warp >> 3;       // scores: 2(M) x 8(N)
    const int wn = warp & 7;
    const float* base = qkv + (size_t)b * Sx * TDx;
    const float* kTb = kT + (size_t)bh * Sx * HDx;
    const float* vTb = vT + (size_t)bh * HDx * Sx;

    auto stageK = [&](int buf, int j0) {
        float* dstb = kvb + buf * 8704;
        #pragma unroll
        for (int i = 0; i < 4; i++) {
            int id = t + i * 512;
            int jj = id >> 4, c = id & 15;
            unsigned d = (unsigned)__cvta_generic_to_shared(&dstb[jj * 68 + c * 4]);
            CP16(d, &kTb[(size_t)(j0 + jj) * HDx + c * 4]);
        }
    };
    // V staged by PV half only (threads 256..511)
    auto stageV = [&](int buf, int j0) {
        float* dstb = kvb + buf * 8704;
        int t2 = t - 256;
        #pragma unroll
        for (int i = 0; i < 8; i++) {
            int id = t2 + i * 256;
            int dd = id >> 5, c = id & 31;
            unsigned d = (unsigned)__cvta_generic_to_shared(&dstb[dd * 132 + c * 4]);
            CP16(d, &vTb[(size_t)dd * Sx + j0 + c * 4]);
        }
    };

    if (t < 256) *(float4*)&mks[4 * t] = *(const float4*)&mask[b * Sx + 4 * t];
    #pragma unroll
    for (int i = 0; i < 4; i++) {
        int id = t + i * 512;
        int rr = id >> 6, d = id & 63;
        qs[rr * 68 + d] = tf32f(base[(size_t)(q0 + rr) * TDx + h * HDx + d]);
    }

    const int ntile = (q0 + 31) / 128 + 1;
    const int Ccols = ntile * 128;

    stageK(0, 0);
    CP_COMMIT();
    __syncthreads();

    // ---- scores ----
    for (int jt = 0; jt < ntile; jt++) {
        const int j0 = jt * 128;
        if (jt + 1 < ntile) { stageK((jt + 1) & 1, (jt + 1) * 128); CP_COMMIT(); CP_WAIT1(); }
        else                { CP_WAIT0(); }
        __syncthreads();
        const float* kvt = kvb + (jt & 1) * 8704;

        float c[2][4];
        #pragma unroll
        for (int i = 0; i < 2; i++)
            #pragma unroll
            for (int j = 0; j < 4; j++) c[i][j] = 0.f;

        #pragma unroll
        for (int ks = 0; ks < 8; ks++) {
            const int kb = ks * 8;
            unsigned a[4];
            const float* ap0 = &qs[(wm * 16 + r) * 68 + kb + cq];
            const float* ap1 = ap0 + 8 * 68;
            a[0] = __float_as_uint(ap0[0]);
            a[1] = __float_as_uint(ap1[0]);
            a[2] = __float_as_uint(ap0[4]);
            a[3] = __float_as_uint(ap1[4]);
            #pragma unroll
            for (int nn = 0; nn < 2; nn++) {
                const float* bp = &kvt[(wn * 16 + nn * 8 + r) * 68 + kb + cq];
                unsigned bf[2] = {__float_as_uint(bp[0]), __float_as_uint(bp[4])};
                mma_tf32(c[nn], a, bf);
            }
        }

        const int qa = q0 + wm * 16 + r;
        const int qb = qa + 8;
        #pragma unroll
        for (int nn = 0; nn < 2; nn++) {
            int jl = wn * 16 + nn * 8 + 2 * cq;
            int jg = j0 + jl;
            float mk0 = mks[jg], mk1 = mks[jg + 1];
            float* s0 = &sc[(wm * 16 + r) * SCS + jg];
            float* s1 = &sc[(wm * 16 + r + 8) * SCS + jg];
            s0[0] = (jg     <= qa) ? tf32f(expapx(fmaf(c[nn][0], 0.125f, mk0))) : 0.f;
            s0[1] = (jg + 1 <= qa) ? tf32f(expapx(fmaf(c[nn][1], 0.125f, mk1))) : 0.f;
            s1[0] = (jg     <= qb) ? tf32f(expapx(fmaf(c[nn][2], 0.125f, mk0))) : 0.f;
            s1[1] = (jg + 1 <= qb) ? tf32f(expapx(fmaf(c[nn][3], 0.125f, mk1))) : 0.f;
        }
        __syncthreads();
    }
    // sc complete for all warps here.

    float oc[2][4];
    #pragma unroll
    for (int i = 0; i < 2; i++)
        #pragma unroll
        for (int j = 0; j < 4; j++) oc[i][j] = 0.f;

    if (warp < 8) {
        // ---- w-store half: rowsum + normalized w store + zero fill ----
        #pragma unroll
        for (int rr = 0; rr < 4; rr++) {
            int row = warp * 4 + rr;
            int q = q0 + row;
            float s = 0.f;
            for (int j4 = lane * 4; j4 < Ccols; j4 += 128) {
                float4 v = *(float4*)&sc[row * SCS + j4];
                s += v.x + v.y + v.z + v.w;
            }
            #pragma unroll
            for (int o = 16; o > 0; o >>= 1) s += __shfl_xor_sync(0xffffffffu, s, o);
            float inv = 1.f / s;
            if (lane == 0) invs[row] = inv;
            size_t wb = ((size_t)(bh * Sx + q)) * Sx;
            for (int j4 = lane * 4; j4 < Ccols; j4 += 128) {
                float4 v = *(float4*)&sc[row * SCS + j4];
                float4 o4 = {v.x * inv, v.y * inv, v.z * inv, v.w * inv};
                *(float4*)&w_out[wb + j4] = o4;
            }
            float4 z = {0.f, 0.f, 0.f, 0.f};
            for (int j4 = Ccols + lane * 4; j4 < Sx; j4 += 128)
                *(float4*)&w_out[wb + j4] = z;
        }
    } else {
        // ---- PV half: 8 warps, 2(M) x 4(N of 16 cols) ----
        const int pwm = (warp - 8) >> 2;
        const int pwn = (warp - 8) & 3;

        stageV(0, 0);
        CP_COMMIT();

        for (int jt = 0; jt < ntile; jt++) {
            const int j0 = jt * 128;
            if (jt + 1 < ntile) { stageV((jt + 1) & 1, (jt + 1) * 128); CP_COMMIT(); CP_WAIT1(); }
            else                { CP_WAIT0(); }
            BARP();
            const float* kvt = kvb + (jt & 1) * 8704;

            #pragma unroll
            for (int ks = 0; ks < 16; ks++) {
                const int kb = ks * 8;
                unsigned a[4];
                const float* ap0 = &sc[(pwm * 16 + r) * SCS + j0 + kb + cq];
                const float* ap1 = ap0 + 8 * SCS;
                a[0] = __float_as_uint(ap0[0]);
                a[1] = __float_as_uint(ap1[0]);
                a[2] = __float_as_uint(ap0[4]);
                a[3] = __float_as_uint(ap1[4]);
                #pragma unroll
                for (int nn = 0; nn < 2; nn++) {
                    const float* bp = &kvt[(pwn * 16 + nn * 8 + r) * 132 + kb + cq];
                    unsigned bf[2] = {__float_as_uint(bp[0]), __float_as_uint(bp[4])};
                    mma_tf32(oc[nn], a, bf);
                }
            }
            BARP();
        }
    }
    __syncthreads();   // invs ready, PV done

    if (warp >= 8) {
        const int pwm = (warp - 8) >> 2;
        const int pwn = (warp - 8) & 3;
        int row_a = pwm * 16 + r, row_b = row_a + 8;
        float ia = invs[row_a], ib = invs[row_b];
        #pragma unroll
        for (int nn = 0; nn < 2; nn++) {
            int d = pwn * 16 + nn * 8 + 2 * cq;
            size_t ra = ((size_t)(b * Sx + q0 + row_a)) * Dx + h * HDx + d;
            size_t rb = ((size_t)(b * Sx + q0 + row_b)) * Dx + h * HDx + d;
            float2 v0 = {tf32f(oc[nn][0] * ia), tf32f(oc[nn][1] * ia)};
            float2 v1 = {tf32f(oc[nn][2] * ib), tf32f(oc[nn][3] * ib)};
            *(float2*)&aout[ra] = v0;
            *(float2*)&aout[rb] = v1;
        }
    }
}

// ---------------------------------------------------------------------------
extern "C" void kernel_launch(void* const* d_in, const int* in_sizes, int n_in,
                              void* d_out, int out_size) {
    const float* x      = (const float*)d_in[0];
    const float* mask   = (const float*)d_in[1];
    const float* w_attn = (const float*)d_in[2];
    const float* b_attn = (const float*)d_in[3];
    const float* w_proj = (const float*)d_in[4];
    const float* b_proj = (const float*)d_in[5];

    float* out_a = (float*)d_out;
    float* out_w = (float*)d_out + (size_t)Bx * Sx * Dx;

    float *qkv, *aout, *xr, *war, *wpr, *kT, *vT;
    cudaGetSymbolAddress((void**)&qkv,  g_qkv);
    cudaGetSymbolAddress((void**)&aout, g_aout);
    cudaGetSymbolAddress((void**)&xr,   g_xr);
    cudaGetSymbolAddress((void**)&war,  g_war);
    cudaGetSymbolAddress((void**)&wpr,  g_wpr);
    cudaGetSymbolAddress((void**)&kT,   g_kT);
    cudaGetSymbolAddress((void**)&vT,   g_vT);

    static const int ATTN_SMEM = 53536 * 4;   // 214144 B
    cudaFuncSetAttribute(attn_mma, cudaFuncAttributeMaxDynamicSharedMemorySize, ATTN_SMEM);
    cudaFuncSetAttribute(gemm_mma, cudaFuncAttributeMaxDynamicSharedMemorySize, GEMM_SMEM);

    {
        int n;
        n = Bx * Sx * Dx / 4;  round_tf32<<<(n + 255) / 256, 256>>>(x, xr, n);
        n = Dx * TDx / 4;      round_tf32<<<(n + 255) / 256, 256>>>(w_attn, war, n);
        n = Dx * Dx / 4;       round_tf32<<<(n + 255) / 256, 256>>>(w_proj, wpr, n);
    }
    {
        dim3 grid(TDx / 128, (Bx * Sx) / 128);
        gemm_mma<<<grid, 256, GEMM_SMEM>>>(xr, war, b_attn, qkv, Bx * Sx, TDx, Dx);
    }
    {
        prep_kT<<<(Bx * Hx * Sx * 16) / 256, 256>>>(qkv, kT);
        dim3 gv(Sx / 64, Bx * Hx);
        prep_vT<<<gv, 256>>>(qkv, vT);
    }
    {
        dim3 grid(Sx / 32, Hx, Bx);
        attn_mma<<<grid, 512, ATTN_SMEM>>>(qkv, kT, vT, mask, out_w, aout);
    }
    {
        dim3 grid(Dx / 128, (Bx * Sx) / 128);
        gemm_mma<<<grid, 256, GEMM_SMEM>>>(aout, wpr, b_proj, out_a, Bx * Sx, Dx, Dx);
    }
}

// round 14
// speedup vs baseline: 1.7600x; 1.0701x over previous
#include <cuda_runtime.h>
#include <cuda.h>
#include <cuda_bf16.h>
#include <cstdint>
#include <math.h>

#define Bx 4
#define Sx 1024
#define Dx 1024
#define Hx 16
#define HDx 64
#define TDx 3072
#define SCS 1028   // scores smem row stride (== 4 mod 32 -> conflict-free frags)

__device__ float g_qkv[Bx * Sx * TDx];
__device__ float g_aout[Bx * Sx * Dx];       // K3 A operand, FRAGMENT-PACKED
__device__ float g_xaf[Bx * Sx * Dx];        // x, A-frag packed, tf32
__device__ float g_waf[Dx * TDx];            // w_attn, B-frag packed, tf32
__device__ float g_wpf[Dx * Dx];             // w_proj, B-frag packed, tf32
__device__ float g_kT[Bx * Hx * Sx * HDx];   // [bh][j][d] tf32 K
__device__ float g_vT[Bx * Hx * HDx * Sx];   // [bh][d][j] tf32 V^T

// ---------------------------------------------------------------------------
__device__ __forceinline__ unsigned f2tf32(float f) {
    unsigned r;
    asm("cvt.rna.tf32.f32 %0, %1;" : "=r"(r) : "f"(f));
    return r;
}
__device__ __forceinline__ float tf32f(float f) { return __uint_as_float(f2tf32(f)); }

__device__ __forceinline__ void mma_tf32(float c[4], const unsigned a[4], const unsigned b[2]) {
    asm volatile("mma.sync.aligned.m16n8k8.row.col.f32.tf32.tf32.f32 "
        "{%0,%1,%2,%3}, {%4,%5,%6,%7}, {%8,%9}, {%0,%1,%2,%3};"
        : "+f"(c[0]), "+f"(c[1]), "+f"(c[2]), "+f"(c[3])
        : "r"(a[0]), "r"(a[1]), "r"(a[2]), "r"(a[3]), "r"(b[0]), "r"(b[1]));
}

__device__ __forceinline__ float expapx(float x) {
    float y = fmaxf(x * 1.4426950408889634f, -80.f);
    float t = y + 12582912.f;
    int   n = __float_as_int(t) - 0x4b400000;
    float f = y - (t - 12582912.f);
    float p = 1.3333558146428443e-3f;
    p = fmaf(p, f, 9.618129842118066e-3f);
    p = fmaf(p, f, 5.550410866482158e-2f);
    p = fmaf(p, f, 2.402265069591007e-1f);
    p = fmaf(p, f, 6.931471805599453e-1f);
    p = fmaf(p, f, 1.0f);
    return __int_as_float(__float_as_int(p) + (n << 23));
}

#define CP16(dst, src) asm volatile("cp.async.cg.shared.global [%0], [%1], 16;" :: "r"(dst), "l"(src))
#define CP_COMMIT()    asm volatile("cp.async.commit_group;")
#define CP_WAIT1()     asm volatile("cp.async.wait_group 1;")
#define CP_WAIT0()     asm volatile("cp.async.wait_group 0;")
#define BARP()         asm volatile("bar.sync 1, 256;" ::: "memory")

// ---------------------------------------------------------------------------
// A-frag pack: A[M][K] -> Af[M/16][K/8][32][4] (tf32-rounded)
// thread tt (= lane in mma) holds a0=(r,cq) a1=(r+8,cq) a2=(r,cq+4) a3=(r+8,cq+4)
__global__ void pack_a(const float* __restrict__ A, float* __restrict__ Af, int K) {
    int i = blockIdx.x * 256 + threadIdx.x;
    int KB = K >> 3;
    int tt = i & 31;
    int kb = (i >> 5) % KB;
    int mb = (i >> 5) / KB;
    int r = tt >> 2, cq = tt & 3;
    size_t row = mb * 16 + r, col = kb * 8 + cq;
    uint4 o;
    o.x = f2tf32(A[row * K + col]);
    o.y = f2tf32(A[(row + 8) * K + col]);
    o.z = f2tf32(A[row * K + col + 4]);
    o.w = f2tf32(A[(row + 8) * K + col + 4]);
    *(uint4*)&Af[(size_t)i * 4] = o;
}

// B-frag pack: B[K][N] -> Bf[N/8][K/8][32][2] (tf32-rounded)
// thread tt holds b0=(k=cq, n=r) b1=(k=cq+4, n=r)
__global__ void pack_b(const float* __restrict__ B, float* __restrict__ Bf, int K, int N) {
    int i = blockIdx.x * 256 + threadIdx.x;
    int KB = K >> 3;
    int tt = i & 31;
    int kb = (i >> 5) % KB;
    int nb = (i >> 5) / KB;
    int r = tt >> 2, cq = tt & 3;
    size_t n = nb * 8 + r, k = kb * 8 + cq;
    uint2 o;
    o.x = f2tf32(B[k * N + n]);
    o.y = f2tf32(B[(k + 4) * N + n]);
    *(uint2*)&Bf[(size_t)i * 2] = o;
}

// kT[bh][j][d] = tf32(K)
__global__ void prep_kT(const float* __restrict__ qkv, float* __restrict__ kT) {
    int i = blockIdx.x * 256 + threadIdx.x;
    int c = i & 15, j = (i >> 4) & 1023, bh = i >> 14;
    int b = bh >> 4, h = bh & 15;
    float4 v = *(const float4*)&qkv[((size_t)(b * Sx + j)) * TDx + Dx + h * HDx + c * 4];
    uint4 o = {f2tf32(v.x), f2tf32(v.y), f2tf32(v.z), f2tf32(v.w)};
    *(uint4*)&kT[(size_t)i * 4] = o;
}

// vT[bh][d][j] = tf32(V)
__global__ void prep_vT(const float* __restrict__ qkv, float* __restrict__ vT) {
    __shared__ float tile[64][68];
    int bh = blockIdx.y, j0 = blockIdx.x * 64;
    int b = bh >> 4, h = bh & 15;
    int t = threadIdx.x;
    #pragma unroll
    for (int i = 0; i < 4; i++) {
        int id = t + i * 256;
        int jj = id >> 4, c = id & 15;
        float4 v = *(const float4*)&qkv[((size_t)(b * Sx + j0 + jj)) * TDx + 2 * Dx + h * HDx + c * 4];
        tile[jj][c * 4 + 0] = tf32f(v.x);
        tile[jj][c * 4 + 1] = tf32f(v.y);
        tile[jj][c * 4 + 2] = tf32f(v.z);
        tile[jj][c * 4 + 3] = tf32f(v.w);
    }
    __syncthreads();
    #pragma unroll
    for (int i = 0; i < 4; i++) {
        int id = t + i * 256;
        int d = id >> 4, c = id & 15;
        float4 o = {tile[c * 4 + 0][d], tile[c * 4 + 1][d], tile[c * 4 + 2][d], tile[c * 4 + 3][d]};
        *(float4*)&vT[((size_t)(bh * HDx + d)) * Sx + j0 + c * 4] = o;
    }
}

// ---------------------------------------------------------------------------
// tf32 GEMM on fragment-packed operands. k-tile 32 (4 kb blocks), 3-stage
// cp.async. A frag load = 1 LDS.128, B frag = 1 LDS.64 (8 LDS / 16 mma per kb).
// Stage = 32KB (A 16KB + B 16KB); 3 stages = 96KB; 2 CTAs/SM.
// ---------------------------------------------------------------------------
#define GEMM_SMEM 98304
__global__ __launch_bounds__(256, 2) void gemm_mma(const float* __restrict__ Af,
                                                   const float* __restrict__ Bf,
                                                   const float* __restrict__ bias,
                                                   float* __restrict__ C,
                                                   int M, int N, int K) {
    extern __shared__ float gsm[];
    float* Asb = gsm;                 // 3 stages of [8 mb][4 kb][32][4]
    float* Bsb = gsm + 3 * 4096;      // 3 stages of [16 nb][4 kb][32][2]

    const int t = threadIdx.x;
    const int warp = t >> 5, lane = t & 31;
    const int wm = warp >> 2, wn = warp & 3;
    const int r = lane >> 2, cq = lane & 3;
    const int row0 = blockIdx.y * 128, col0 = blockIdx.x * 128;
    const int rowb0 = row0 >> 4, colb0 = col0 >> 3;
    const int KB = K >> 3;

    float acc[4][4][4];
    #pragma unroll
    for (int i = 0; i < 4; i++)
        #pragma unroll
        for (int j = 0; j < 4; j++)
            #pragma unroll
            for (int k = 0; k < 4; k++) acc[i][j][k] = 0.f;

    // stage load: A 8 mb x 4 kb x 512B, B 16 nb x 4 kb x 256B (1024+1024 CP16)
    auto loadG = [&](int st, int kb0) {
        float* As = Asb + st * 4096;
        float* Bs = Bsb + st * 4096;
        #pragma unroll
        for (int i = 0; i < 4; i++) {
            int id = t + i * 256;
            int mb = id >> 7, remA = id & 127, kbA = remA >> 5, cA = remA & 31;
            unsigned da = (unsigned)__cvta_generic_to_shared(&As[(mb * 4 + kbA) * 128 + cA * 4]);
            CP16(da, &Af[((size_t)(rowb0 + mb) * KB + kb0 + kbA) * 128 + cA * 4]);
            int nb = id >> 6, remB = id & 63, kbB = remB >> 4, cB = remB & 15;
            unsigned db = (unsigned)__cvta_generic_to_shared(&Bs[(nb * 4 + kbB) * 64 + cB * 4]);
            CP16(db, &Bf[((size_t)(colb0 + nb) * KB + kb0 + kbB) * 64 + cB * 4]);
        }
    };

    loadG(0, 0); CP_COMMIT();
    loadG(1, 4); CP_COMMIT();

    const int NT = K / 32;
    int st = 0;
    for (int kt = 0; kt < NT; kt++) {
        if (kt + 1 < NT) CP_WAIT1(); else CP_WAIT0();
        __syncthreads();
        if (kt + 2 < NT) {
            int st2 = st + 2; if (st2 >= 3) st2 -= 3;
            loadG(st2, (kt + 2) * 4);
            CP_COMMIT();
        }
        const float* As = Asb + st * 4096;
        const float* Bs = Bsb + st * 4096;

        #pragma unroll
        for (int kb = 0; kb < 4; kb++) {
            unsigned a[4][4], b[4][2];
            #pragma unroll
            for (int mm = 0; mm < 4; mm++) {
                uint4 v = *(const uint4*)&As[((wm * 4 + mm) * 4 + kb) * 128 + lane * 4];
                a[mm][0] = v.x; a[mm][1] = v.y; a[mm][2] = v.z; a[mm][3] = v.w;
            }
            #pragma unroll
            for (int nn = 0; nn < 4; nn++) {
                uint2 v = *(const uint2*)&Bs[((wn * 4 + nn) * 4 + kb) * 64 + lane * 2];
                b[nn][0] = v.x; b[nn][1] = v.y;
            }
            #pragma unroll
            for (int mm = 0; mm < 4; mm++)
                #pragma unroll
                for (int nn = 0; nn < 4; nn++)
                    mma_tf32(acc[mm][nn], a[mm], b[nn]);
        }
        if (++st == 3) st = 0;
    }

    #pragma unroll
    for (int mm = 0; mm < 4; mm++) {
        int r0 = row0 + wm * 64 + mm * 16 + r;
        #pragma unroll
        for (int nn = 0; nn < 4; nn++) {
            int c0 = col0 + wn * 32 + nn * 8 + 2 * cq;
            float2 bv = *(const float2*)&bias[c0];
            float2 o0 = {acc[mm][nn][0] + bv.x, acc[mm][nn][1] + bv.y};
            float2 o1 = {acc[mm][nn][2] + bv.x, acc[mm][nn][3] + bv.y};
            *(float2*)&C[(size_t)r0 * N + c0] = o0;
            *(float2*)&C[(size_t)(r0 + 8) * N + c0] = o1;
        }
    }
}

// ---------------------------------------------------------------------------
// Tensor-core attention, 512 threads: scores all tiles, then warps 0-7
// rowsum+w-store overlapped with warps 8-15 PV mma. PV epilogue writes aout
// directly in A-fragment layout for K3.
// ---------------------------------------------------------------------------
__global__ __launch_bounds__(512) void attn_mma(const float* __restrict__ qkv,
                                                const float* __restrict__ kT,
                                                const float* __restrict__ vT,
                                                const float* __restrict__ mask,
                                                float* __restrict__ w_out,
                                                float* __restrict__ aout) {
    extern __shared__ float sm[];
    float* sc   = sm;            // [32][SCS]
    float* qs   = sm + 32896;    // [32][68]
    float* kvb  = sm + 35072;    // 2 x 8704
    float* mks  = sm + 52480;    // [1024]
    float* invs = sm + 53504;    // [32]

    const int q0 = blockIdx.x * 32;
    const int h  = blockIdx.y;
    const int b  = blockIdx.z;
    const int bh = b * Hx + h;
    const int t  = threadIdx.x;
    const int warp = t >> 5, lane = t & 31;
    const int r = lane >> 2, cq = lane & 3;
    const int wm = warp >> 3;       // scores: 2(M) x 8(N)
    const int wn = warp & 7;
    const float* base = qkv + (size_t)b * Sx * TDx;
    const float* kTb = kT + (size_t)bh * Sx * HDx;
    const float* vTb = vT + (size_t)bh * HDx * Sx;

    auto stageK = [&](int buf, int j0) {
        float* dstb = kvb + buf * 8704;
        #pragma unroll
        for (int i = 0; i < 4; i++) {
            int id = t + i * 512;
            int jj = id >> 4, c = id & 15;
            unsigned d = (unsigned)__cvta_generic_to_shared(&dstb[jj * 68 + c * 4]);
            CP16(d, &kTb[(size_t)(j0 + jj) * HDx + c * 4]);
        }
    };
    auto stageV = [&](int buf, int j0) {
        float* dstb = kvb + buf * 8704;
        int t2 = t - 256;
        #pragma unroll
        for (int i = 0; i < 8; i++) {
            int id = t2 + i * 256;
            int dd = id >> 5, c = id & 31;
            unsigned d = (unsigned)__cvta_generic_to_shared(&dstb[dd * 132 + c * 4]);
            CP16(d, &vTb[(size_t)dd * Sx + j0 + c * 4]);
        }
    };

    if (t < 256) *(float4*)&mks[4 * t] = *(const float4*)&mask[b * Sx + 4 * t];
    #pragma unroll
    for (int i = 0; i < 4; i++) {
        int id = t + i * 512;
        int rr = id >> 6, d = id & 63;
        qs[rr * 68 + d] = tf32f(base[(size_t)(q0 + rr) * TDx + h * HDx + d]);
    }

    const int ntile = (q0 + 31) / 128 + 1;
    const int Ccols = ntile * 128;

    stageK(0, 0);
    CP_COMMIT();
    __syncthreads();

    // ---- scores ----
    for (int jt = 0; jt < ntile; jt++) {
        const int j0 = jt * 128;
        if (jt + 1 < ntile) { stageK((jt + 1) & 1, (jt + 1) * 128); CP_COMMIT(); CP_WAIT1(); }
        else                { CP_WAIT0(); }
        __syncthreads();
        const float* kvt = kvb + (jt & 1) * 8704;

        float c[2][4];
        #pragma unroll
        for (int i = 0; i < 2; i++)
            #pragma unroll
            for (int j = 0; j < 4; j++) c[i][j] = 0.f;

        #pragma unroll
        for (int ks = 0; ks < 8; ks++) {
            const int kb = ks * 8;
            unsigned a[4];
            const float* ap0 = &qs[(wm * 16 + r) * 68 + kb + cq];
            const float* ap1 = ap0 + 8 * 68;
            a[0] = __float_as_uint(ap0[0]);
            a[1] = __float_as_uint(ap1[0]);
            a[2] = __float_as_uint(ap0[4]);
            a[3] = __float_as_uint(ap1[4]);
            #pragma unroll
            for (int nn = 0; nn < 2; nn++) {
                const float* bp = &kvt[(wn * 16 + nn * 8 + r) * 68 + kb + cq];
                unsigned bf[2] = {__float_as_uint(bp[0]), __float_as_uint(bp[4])};
                mma_tf32(c[nn], a, bf);
            }
        }

        const int qa = q0 + wm * 16 + r;
        const int qb = qa + 8;
        #pragma unroll
        for (int nn = 0; nn < 2; nn++) {
            int jl = wn * 16 + nn * 8 + 2 * cq;
            int jg = j0 + jl;
            float mk0 = mks[jg], mk1 = mks[jg + 1];
            float* s0 = &sc[(wm * 16 + r) * SCS + jg];
            float* s1 = &sc[(wm * 16 + r + 8) * SCS + jg];
            s0[0] = (jg     <= qa) ? tf32f(expapx(fmaf(c[nn][0], 0.125f, mk0))) : 0.f;
            s0[1] = (jg + 1 <= qa) ? tf32f(expapx(fmaf(c[nn][1], 0.125f, mk1))) : 0.f;
            s1[0] = (jg     <= qb) ? tf32f(expapx(fmaf(c[nn][2], 0.125f, mk0))) : 0.f;
            s1[1] = (jg + 1 <= qb) ? tf32f(expapx(fmaf(c[nn][3], 0.125f, mk1))) : 0.f;
        }
        __syncthreads();
    }
    // sc complete for all warps here.

    float oc[2][4];
    #pragma unroll
    for (int i = 0; i < 2; i++)
        #pragma unroll
        for (int j = 0; j < 4; j++) oc[i][j] = 0.f;

    if (warp < 8) {
        // ---- w-store half: rowsum + normalized w store + zero fill ----
        #pragma unroll
        for (int rr = 0; rr < 4; rr++) {
            int row = warp * 4 + rr;
            int q = q0 + row;
            float s = 0.f;
            for (int j4 = lane * 4; j4 < Ccols; j4 += 128) {
                float4 v = *(float4*)&sc[row * SCS + j4];
                s += v.x + v.y + v.z + v.w;
            }
            #pragma unroll
            for (int o = 16; o > 0; o >>= 1) s += __shfl_xor_sync(0xffffffffu, s, o);
            float inv = 1.f / s;
            if (lane == 0) invs[row] = inv;
            size_t wb = ((size_t)(bh * Sx + q)) * Sx;
            for (int j4 = lane * 4; j4 < Ccols; j4 += 128) {
                float4 v = *(float4*)&sc[row * SCS + j4];
                float4 o4 = {v.x * inv, v.y * inv, v.z * inv, v.w * inv};
                *(float4*)&w_out[wb + j4] = o4;
            }
            float4 z = {0.f, 0.f, 0.f, 0.f};
            for (int j4 = Ccols + lane * 4; j4 < Sx; j4 += 128)
                *(float4*)&w_out[wb + j4] = z;
        }
    } else {
        // ---- PV half: 8 warps, 2(M) x 4(N of 16 cols) ----
        const int pwm = (warp - 8) >> 2;
        const int pwn = (warp - 8) & 3;

        stageV(0, 0);
        CP_COMMIT();

        for (int jt = 0; jt < ntile; jt++) {
            const int j0 = jt * 128;
            if (jt + 1 < ntile) { stageV((jt + 1) & 1, (jt + 1) * 128); CP_COMMIT(); CP_WAIT1(); }
            else                { CP_WAIT0(); }
            BARP();
            const float* kvt = kvb + (jt & 1) * 8704;

            #pragma unroll
            for (int ks = 0; ks < 16; ks++) {
                const int kb = ks * 8;
                unsigned a[4];
                const float* ap0 = &sc[(pwm * 16 + r) * SCS + j0 + kb + cq];
                const float* ap1 = ap0 + 8 * SCS;
                a[0] = __float_as_uint(ap0[0]);
                a[1] = __float_as_uint(ap1[0]);
                a[2] = __float_as_uint(ap0[4]);
                a[3] = __float_as_uint(ap1[4]);
                #pragma unroll
                for (int nn = 0; nn < 2; nn++) {
                    const float* bp = &kvt[(pwn * 16 + nn * 8 + r) * 132 + kb + cq];
                    unsigned bf[2] = {__float_as_uint(bp[0]), __float_as_uint(bp[4])};
                    mma_tf32(oc[nn], a, bf);
                }
            }
            BARP();
        }
    }
    __syncthreads();   // invs ready, PV done

    if (warp >= 8) {
        const int pwm = (warp - 8) >> 2;
        const int pwn = (warp - 8) & 3;
        float ia = invs[pwm * 16 + r], ib = invs[pwm * 16 + r + 8];
        // write aout in A-frag layout: Af[mb][kb(128)][32][4]
        int mb = ((b * Sx + q0) >> 4) + pwm;
        #pragma unroll
        for (int nn = 0; nn < 2; nn++) {
            int d = pwn * 16 + nn * 8 + 2 * cq;
            int gcol = h * HDx + d;
            int kb = gcol >> 3, cc = gcol & 7;
            int slot = (cc < 4) ? 0 : 2;
            size_t base_ = ((size_t)mb * 128 + kb) * 32;
            float2 w0 = {tf32f(oc[nn][0] * ia), tf32f(oc[nn][2] * ib)};  // col d: rows r, r+8
            float2 w1 = {tf32f(oc[nn][1] * ia), tf32f(oc[nn][3] * ib)};  // col d+1
            int tt0 = r * 4 + (cc & 3);
            int tt1 = r * 4 + ((cc + 1) & 3);
            *(float2*)&aout[(base_ + tt0) * 4 + slot] = w0;
            *(float2*)&aout[(base_ + tt1) * 4 + slot] = w1;
        }
    }
}

// ---------------------------------------------------------------------------
extern "C" void kernel_launch(void* const* d_in, const int* in_sizes, int n_in,
                              void* d_out, int out_size) {
    const float* x      = (const float*)d_in[0];
    const float* mask   = (const float*)d_in[1];
    const float* w_attn = (const float*)d_in[2];
    const float* b_attn = (const float*)d_in[3];
    const float* w_proj = (const float*)d_in[4];
    const float* b_proj = (const float*)d_in[5];

    float* out_a = (float*)d_out;
    float* out_w = (float*)d_out + (size_t)Bx * Sx * Dx;

    float *qkv, *aout, *xaf, *waf, *wpf, *kT, *vT;
    cudaGetSymbolAddress((void**)&qkv,  g_qkv);
    cudaGetSymbolAddress((void**)&aout, g_aout);
    cudaGetSymbolAddress((void**)&xaf,  g_xaf);
    cudaGetSymbolAddress((void**)&waf,  g_waf);
    cudaGetSymbolAddress((void**)&wpf,  g_wpf);
    cudaGetSymbolAddress((void**)&kT,   g_kT);
    cudaGetSymbolAddress((void**)&vT,   g_vT);

    static const int ATTN_SMEM = 53536 * 4;   // 214144 B
    cudaFuncSetAttribute(attn_mma, cudaFuncAttributeMaxDynamicSharedMemorySize, ATTN_SMEM);
    cudaFuncSetAttribute(gemm_mma, cudaFuncAttributeMaxDynamicSharedMemorySize, GEMM_SMEM);

    // fragment-pack inputs (tf32 rounding fused)
    {
        pack_a<<<(Bx * Sx * Dx / 4) / 256, 256>>>(x, xaf, Dx);
        pack_b<<<(Dx * TDx / 2) / 256, 256>>>(w_attn, waf, Dx, TDx);
        pack_b<<<(Dx * Dx / 2) / 256, 256>>>(w_proj, wpf, Dx, Dx);
    }
    // K1: qkv = x @ w_attn + b_attn
    {
        dim3 grid(TDx / 128, (Bx * Sx) / 128);
        gemm_mma<<<grid, 256, GEMM_SMEM>>>(xaf, waf, b_attn, qkv, Bx * Sx, TDx, Dx);
    }
    {
        prep_kT<<<(Bx * Hx * Sx * 16) / 256, 256>>>(qkv, kT);
        dim3 gv(Sx / 64, Bx * Hx);
        prep_vT<<<gv, 256>>>(qkv, vT);
    }
    {
        dim3 grid(Sx / 32, Hx, Bx);
        attn_mma<<<grid, 512, ATTN_SMEM>>>(qkv, kT, vT, mask, out_w, aout);
    }
    // K3: a = aout @ w_proj + b_proj  (aout already frag-packed by attn)
    {
        dim3 grid(Dx / 128, (Bx * Sx) / 128);
        gemm_mma<<<grid, 256, GEMM_SMEM>>>(aout, wpf, b_proj, out_a, Bx * Sx, Dx, Dx);
    }
}

// round 15
// speedup vs baseline: 1.8631x; 1.0585x over previous
#include <cuda_runtime.h>
#include <cuda.h>
#include <cuda_bf16.h>
#include <cstdint>
#include <math.h>

#define Bx 4
#define Sx 1024
#define Dx 1024
#define Hx 16
#define HDx 64
#define TDx 3072
#define SCS 1028   // scores smem row stride (== 4 mod 32 -> conflict-free frags)

__device__ float g_qkv[Bx * Sx * TDx];
__device__ float g_aout[Bx * Sx * Dx];       // K3 A operand, FRAGMENT-PACKED
__device__ float g_xaf[Bx * Sx * Dx];        // x, A-frag packed, tf32
__device__ float g_waf[Dx * TDx];            // w_attn, B-frag packed, tf32
__device__ float g_wpf[Dx * Dx];             // w_proj, B-frag packed, tf32
__device__ float g_kTf[Bx * Hx * Sx * HDx];  // K, B-frag packed [bh][jb][kb][32][2]
__device__ float g_vTf[Bx * Hx * HDx * Sx];  // V, B-frag packed [bh][db][jbk][32][2]

// ---------------------------------------------------------------------------
__device__ __forceinline__ unsigned f2tf32(float f) {
    unsigned r;
    asm("cvt.rna.tf32.f32 %0, %1;" : "=r"(r) : "f"(f));
    return r;
}
__device__ __forceinline__ float tf32f(float f) { return __uint_as_float(f2tf32(f)); }

__device__ __forceinline__ void mma_tf32(float c[4], const unsigned a[4], const unsigned b[2]) {
    asm volatile("mma.sync.aligned.m16n8k8.row.col.f32.tf32.tf32.f32 "
        "{%0,%1,%2,%3}, {%4,%5,%6,%7}, {%8,%9}, {%0,%1,%2,%3};"
        : "+f"(c[0]), "+f"(c[1]), "+f"(c[2]), "+f"(c[3])
        : "r"(a[0]), "r"(a[1]), "r"(a[2]), "r"(a[3]), "r"(b[0]), "r"(b[1]));
}

__device__ __forceinline__ float expapx(float x) {
    float y = fmaxf(x * 1.4426950408889634f, -80.f);
    float t = y + 12582912.f;
    int   n = __float_as_int(t) - 0x4b400000;
    float f = y - (t - 12582912.f);
    float p = 1.3333558146428443e-3f;
    p = fmaf(p, f, 9.618129842118066e-3f);
    p = fmaf(p, f, 5.550410866482158e-2f);
    p = fmaf(p, f, 2.402265069591007e-1f);
    p = fmaf(p, f, 6.931471805599453e-1f);
    p = fmaf(p, f, 1.0f);
    return __int_as_float(__float_as_int(p) + (n << 23));
}

#define CP16(dst, src) asm volatile("cp.async.cg.shared.global [%0], [%1], 16;" :: "r"(dst), "l"(src))
#define CP_COMMIT()    asm volatile("cp.async.commit_group;")
#define CP_WAIT1()     asm volatile("cp.async.wait_group 1;")
#define CP_WAIT0()     asm volatile("cp.async.wait_group 0;")
#define BARP()         asm volatile("bar.sync 1, 256;" ::: "memory")

// ---------------------------------------------------------------------------
// A-frag pack: A[M][K] -> Af[M/16][K/8][32][4] (tf32-rounded)
__global__ void pack_a(const float* __restrict__ A, float* __restrict__ Af, int K) {
    int i = blockIdx.x * 256 + threadIdx.x;
    int KB = K >> 3;
    int tt = i & 31;
    int kb = (i >> 5) % KB;
    int mb = (i >> 5) / KB;
    int r = tt >> 2, cq = tt & 3;
    size_t row = mb * 16 + r, col = kb * 8 + cq;
    uint4 o;
    o.x = f2tf32(A[row * K + col]);
    o.y = f2tf32(A[(row + 8) * K + col]);
    o.z = f2tf32(A[row * K + col + 4]);
    o.w = f2tf32(A[(row + 8) * K + col + 4]);
    *(uint4*)&Af[(size_t)i * 4] = o;
}

// B-frag pack: B[K][N] -> Bf[N/8][K/8][32][2] (tf32-rounded)
__global__ void pack_b(const float* __restrict__ B, float* __restrict__ Bf, int K, int N) {
    int i = blockIdx.x * 256 + threadIdx.x;
    int KB = K >> 3;
    int tt = i & 31;
    int kb = (i >> 5) % KB;
    int nb = (i >> 5) / KB;
    int r = tt >> 2, cq = tt & 3;
    size_t n = nb * 8 + r, k = kb * 8 + cq;
    uint2 o;
    o.x = f2tf32(B[k * N + n]);
    o.y = f2tf32(B[(k + 4) * N + n]);
    *(uint2*)&Bf[(size_t)i * 2] = o;
}

// K B-frag pack: kTf[bh][jb(128)][kb(8)][32][2]; b0=K[j=jb*8+r][d=kb*8+cq], b1=d+4
__global__ void prep_kTf(const float* __restrict__ qkv, float* __restrict__ kTf) {
    int i = blockIdx.x * 256 + threadIdx.x;
    int tt = i & 31;
    int kb = (i >> 5) & 7;
    int jb = (i >> 8) & 127;
    int bh = i >> 15;
    int b = bh >> 4, h = bh & 15;
    int r = tt >> 2, cq = tt & 3;
    const float* src = &qkv[((size_t)(b * Sx + jb * 8 + r)) * TDx + Dx + h * HDx + kb * 8 + cq];
    uint2 o = {f2tf32(src[0]), f2tf32(src[4])};
    *(uint2*)&kTf[(size_t)i * 2] = o;
}

// V B-frag pack: vTf[bh][db(8)][jbk(128)][32][2]; b0=V[j=jbk*8+cq][d=db*8+r], b1=j+4
__global__ void prep_vTf(const float* __restrict__ qkv, float* __restrict__ vTf) {
    int i = blockIdx.x * 256 + threadIdx.x;
    int tt = i & 31;
    int jbk = (i >> 5) & 127;
    int db = (i >> 12) & 7;
    int bh = i >> 15;
    int b = bh >> 4, h = bh & 15;
    int r = tt >> 2, cq = tt & 3;
    const float* src = &qkv[((size_t)(b * Sx + jbk * 8 + cq)) * TDx + 2 * Dx + h * HDx + db * 8 + r];
    uint2 o = {f2tf32(src[0]), f2tf32(src[4 * TDx])};
    *(uint2*)&vTf[(size_t)i * 2] = o;
}

// ---------------------------------------------------------------------------
// tf32 GEMM on fragment-packed operands (unchanged from R14).
// ---------------------------------------------------------------------------
#define GEMM_SMEM 98304
__global__ __launch_bounds__(256, 2) void gemm_mma(const float* __restrict__ Af,
                                                   const float* __restrict__ Bf,
                                                   const float* __restrict__ bias,
                                                   float* __restrict__ C,
                                                   int M, int N, int K) {
    extern __shared__ float gsm[];
    float* Asb = gsm;
    float* Bsb = gsm + 3 * 4096;

    const int t = threadIdx.x;
    const int warp = t >> 5, lane = t & 31;
    const int wm = warp >> 2, wn = warp & 3;
    const int r = lane >> 2, cq = lane & 3;
    const int row0 = blockIdx.y * 128, col0 = blockIdx.x * 128;
    const int rowb0 = row0 >> 4, colb0 = col0 >> 3;
    const int KB = K >> 3;

    float acc[4][4][4];
    #pragma unroll
    for (int i = 0; i < 4; i++)
        #pragma unroll
        for (int j = 0; j < 4; j++)
            #pragma unroll
            for (int k = 0; k < 4; k++) acc[i][j][k] = 0.f;

    auto loadG = [&](int st, int kb0) {
        float* As = Asb + st * 4096;
        float* Bs = Bsb + st * 4096;
        #pragma unroll
        for (int i = 0; i < 4; i++) {
            int id = t + i * 256;
            int mb = id >> 7, remA = id & 127, kbA = remA >> 5, cA = remA & 31;
            unsigned da = (unsigned)__cvta_generic_to_shared(&As[(mb * 4 + kbA) * 128 + cA * 4]);
            CP16(da, &Af[((size_t)(rowb0 + mb) * KB + kb0 + kbA) * 128 + cA * 4]);
            int nb = id >> 6, remB = id & 63, kbB = remB >> 4, cB = remB & 15;
            unsigned db = (unsigned)__cvta_generic_to_shared(&Bs[(nb * 4 + kbB) * 64 + cB * 4]);
            CP16(db, &Bf[((size_t)(colb0 + nb) * KB + kb0 + kbB) * 64 + cB * 4]);
        }
    };

    loadG(0, 0); CP_COMMIT();
    loadG(1, 4); CP_COMMIT();

    const int NT = K / 32;
    int st = 0;
    for (int kt = 0; kt < NT; kt++) {
        if (kt + 1 < NT) CP_WAIT1(); else CP_WAIT0();
        __syncthreads();
        if (kt + 2 < NT) {
            int st2 = st + 2; if (st2 >= 3) st2 -= 3;
            loadG(st2, (kt + 2) * 4);
            CP_COMMIT();
        }
        const float* As = Asb + st * 4096;
        const float* Bs = Bsb + st * 4096;

        #pragma unroll
        for (int kb = 0; kb < 4; kb++) {
            unsigned a[4][4], b[4][2];
            #pragma unroll
            for (int mm = 0; mm < 4; mm++) {
                uint4 v = *(const uint4*)&As[((wm * 4 + mm) * 4 + kb) * 128 + lane * 4];
                a[mm][0] = v.x; a[mm][1] = v.y; a[mm][2] = v.z; a[mm][3] = v.w;
            }
            #pragma unroll
            for (int nn = 0; nn < 4; nn++) {
                uint2 v = *(const uint2*)&Bs[((wn * 4 + nn) * 4 + kb) * 64 + lane * 2];
                b[nn][0] = v.x; b[nn][1] = v.y;
            }
            #pragma unroll
            for (int mm = 0; mm < 4; mm++)
                #pragma unroll
                for (int nn = 0; nn < 4; nn++)
                    mma_tf32(acc[mm][nn], a[mm], b[nn]);
        }
        if (++st == 3) st = 0;
    }

    #pragma unroll
    for (int mm = 0; mm < 4; mm++) {
        int r0 = row0 + wm * 64 + mm * 16 + r;
        #pragma unroll
        for (int nn = 0; nn < 4; nn++) {
            int c0 = col0 + wn * 32 + nn * 8 + 2 * cq;
            float2 bv = *(const float2*)&bias[c0];
            float2 o0 = {acc[mm][nn][0] + bv.x, acc[mm][nn][1] + bv.y};
            float2 o1 = {acc[mm][nn][2] + bv.x, acc[mm][nn][3] + bv.y};
            *(float2*)&C[(size_t)r0 * N + c0] = o0;
            *(float2*)&C[(size_t)(r0 + 8) * N + c0] = o1;
        }
    }
}

// ---------------------------------------------------------------------------
// Tensor-core attention, 512 threads, fragment-packed K/V/Q operands.
// Reversed q0 mapping for causal load balance. Smem (floats):
//   sc 0..32895, qsf 32896..34943, kvb 34944..51327 (2x8192),
//   mks 51328..52351, invs 52352..52383  -> 52384 floats = 209536 B
// ---------------------------------------------------------------------------
__global__ __launch_bounds__(512) void attn_mma(const float* __restrict__ qkv,
                                                const float* __restrict__ kTf,
                                                const float* __restrict__ vTf,
                                                const float* __restrict__ mask,
                                                float* __restrict__ w_out,
                                                float* __restrict__ aout) {
    extern __shared__ float sm[];
    float* sc   = sm;
    float* qsf  = sm + 32896;
    float* kvb  = sm + 34944;
    float* mks  = sm + 51328;
    float* invs = sm + 52352;

    const int q0 = (Sx / 32 - 1 - blockIdx.x) * 32;   // biggest work first
    const int h  = blockIdx.y;
    const int b  = blockIdx.z;
    const int bh = b * Hx + h;
    const int t  = threadIdx.x;
    const int warp = t >> 5, lane = t & 31;
    const int r = lane >> 2, cq = lane & 3;
    const int wm = warp >> 3;       // scores: 2(M) x 8(N)
    const int wn = warp & 7;
    const float* base = qkv + (size_t)b * Sx * TDx;
    const float* kTfb = kTf + (size_t)bh * Sx * HDx;   // [jb][kb][32][2]
    const float* vTfb = vTf + (size_t)bh * HDx * Sx;   // [db][jbk][32][2]

    // stage K tile (contiguous 8192 floats) by all 512 threads
    auto stageK = [&](int buf, int jt) {
        float* dstb = kvb + buf * 8192;
        const float* src = kTfb + (size_t)jt * 8192;
        #pragma unroll
        for (int i = 0; i < 4; i++) {
            int id = t + i * 512;
            unsigned d = (unsigned)__cvta_generic_to_shared(&dstb[id * 4]);
            CP16(d, &src[id * 4]);
        }
    };
    // stage V tile by PV half only (threads 256..511): [db][kbl][32][2]
    auto stageV = [&](int buf, int jt) {
        float* dstb = kvb + buf * 8192;
        int t2 = t - 256;
        #pragma unroll
        for (int i = 0; i < 8; i++) {
            int id = t2 + i * 256;
            int db = id >> 8, rem = id & 255;
            unsigned d = (unsigned)__cvta_generic_to_shared(&dstb[(db * 256 + rem) * 4]);
            CP16(d, &vTfb[(size_t)db * 8192 + (size_t)jt * 1024 + rem * 4]);
        }
    };

    if (t < 256) *(float4*)&mks[4 * t] = *(const float4*)&mask[b * Sx + 4 * t];
    // Q A-frag staging: 16 groups (2 mb x 8 kb) x 32 threads
    {
        int g = t >> 5, tt = t & 31;
        int mbq = g >> 3, kbq = g & 7;
        int rr = tt >> 2, cc = tt & 3;
        const float* q0p = &base[(size_t)(q0 + mbq * 16 + rr) * TDx + h * HDx + kbq * 8 + cc];
        const float* q1p = q0p + 8 * TDx;
        uint4 qa;
        qa.x = f2tf32(q0p[0]); qa.y = f2tf32(q1p[0]);
        qa.z = f2tf32(q0p[4]); qa.w = f2tf32(q1p[4]);
        *(uint4*)&qsf[g * 128 + tt * 4] = qa;
    }

    const int ntile = (q0 + 31) / 128 + 1;
    const int Ccols = ntile * 128;

    stageK(0, 0);
    CP_COMMIT();
    __syncthreads();

    // ---- scores ----
    for (int jt = 0; jt < ntile; jt++) {
        const int j0 = jt * 128;
        if (jt + 1 < ntile) { stageK((jt + 1) & 1, jt + 1); CP_COMMIT(); CP_WAIT1(); }
        else                { CP_WAIT0(); }
        __syncthreads();
        const float* kst = kvb + (jt & 1) * 8192;

        float c[2][4];
        #pragma unroll
        for (int i = 0; i < 2; i++)
            #pragma unroll
            for (int j = 0; j < 4; j++) c[i][j] = 0.f;

        #pragma unroll
        for (int ks = 0; ks < 8; ks++) {
            unsigned a[4];
            uint4 av = *(const uint4*)&qsf[(wm * 8 + ks) * 128 + lane * 4];
            a[0] = av.x; a[1] = av.y; a[2] = av.z; a[3] = av.w;
            #pragma unroll
            for (int nn = 0; nn < 2; nn++) {
                uint2 bv = *(const uint2*)&kst[((wn * 2 + nn) * 8 + ks) * 64 + lane * 2];
                unsigned bf[2] = {bv.x, bv.y};
                mma_tf32(c[nn], a, bf);
            }
        }

        const int qa_ = q0 + wm * 16 + r;
        const int qb_ = qa_ + 8;
        #pragma unroll
        for (int nn = 0; nn < 2; nn++) {
            int jl = wn * 16 + nn * 8 + 2 * cq;
            int jg = j0 + jl;
            float mk0 = mks[jg], mk1 = mks[jg + 1];
            float* s0 = &sc[(wm * 16 + r) * SCS + jg];
            float* s1 = &sc[(wm * 16 + r + 8) * SCS + jg];
            s0[0] = (jg     <= qa_) ? tf32f(expapx(fmaf(c[nn][0], 0.125f, mk0))) : 0.f;
            s0[1] = (jg + 1 <= qa_) ? tf32f(expapx(fmaf(c[nn][1], 0.125f, mk1))) : 0.f;
            s1[0] = (jg     <= qb_) ? tf32f(expapx(fmaf(c[nn][2], 0.125f, mk0))) : 0.f;
            s1[1] = (jg + 1 <= qb_) ? tf32f(expapx(fmaf(c[nn][3], 0.125f, mk1))) : 0.f;
        }
        __syncthreads();
    }
    // sc complete for all warps here.

    float oc[2][4];
    #pragma unroll
    for (int i = 0; i < 2; i++)
        #pragma unroll
        for (int j = 0; j < 4; j++) oc[i][j] = 0.f;

    if (warp < 8) {
        // ---- w-store half: rowsum + normalized w store + zero fill ----
        #pragma unroll
        for (int rr = 0; rr < 4; rr++) {
            int row = warp * 4 + rr;
            int q = q0 + row;
            float s = 0.f;
            for (int j4 = lane * 4; j4 < Ccols; j4 += 128) {
                float4 v = *(float4*)&sc[row * SCS + j4];
                s += v.x + v.y + v.z + v.w;
            }
            #pragma unroll
            for (int o = 16; o > 0; o >>= 1) s += __shfl_xor_sync(0xffffffffu, s, o);
            float inv = 1.f / s;
            if (lane == 0) invs[row] = inv;
            size_t wb = ((size_t)(bh * Sx + q)) * Sx;
            for (int j4 = lane * 4; j4 < Ccols; j4 += 128) {
                float4 v = *(float4*)&sc[row * SCS + j4];
                float4 o4 = {v.x * inv, v.y * inv, v.z * inv, v.w * inv};
                *(float4*)&w_out[wb + j4] = o4;
            }
            float4 z = {0.f, 0.f, 0.f, 0.f};
            for (int j4 = Ccols + lane * 4; j4 < Sx; j4 += 128)
                *(float4*)&w_out[wb + j4] = z;
        }
    } else {
        // ---- PV half: 8 warps, 2(M) x 4(N of 16 cols) ----
        const int pwm = (warp - 8) >> 2;
        const int pwn = (warp - 8) & 3;

        stageV(0, 0);
        CP_COMMIT();

        for (int jt = 0; jt < ntile; jt++) {
            const int j0 = jt * 128;
            if (jt + 1 < ntile) { stageV((jt + 1) & 1, jt + 1); CP_COMMIT(); CP_WAIT1(); }
            else                { CP_WAIT0(); }
            BARP();
            const float* vst = kvb + (jt & 1) * 8192;

            #pragma unroll
            for (int ks = 0; ks < 16; ks++) {
                const int kb = ks * 8;
                unsigned a[4];
                const float* ap0 = &sc[(pwm * 16 + r) * SCS + j0 + kb + cq];
                const float* ap1 = ap0 + 8 * SCS;
                a[0] = __float_as_uint(ap0[0]);
                a[1] = __float_as_uint(ap1[0]);
                a[2] = __float_as_uint(ap0[4]);
                a[3] = __float_as_uint(ap1[4]);
                #pragma unroll
                for (int nn = 0; nn < 2; nn++) {
                    uint2 bv = *(const uint2*)&vst[((pwn * 2 + nn) * 16 + ks) * 64 + lane * 2];
                    unsigned bf[2] = {bv.x, bv.y};
                    mma_tf32(oc[nn], a, bf);
                }
            }
            BARP();
        }
    }
    __syncthreads();   // invs ready, PV done

    if (warp >= 8) {
        const int pwm = (warp - 8) >> 2;
        const int pwn = (warp - 8) & 3;
        float ia = invs[pwm * 16 + r], ib = invs[pwm * 16 + r + 8];
        // write aout in A-frag layout: Af[mb][kb(128)][32][4]
        int mb = ((b * Sx + q0) >> 4) + pwm;
        #pragma unroll
        for (int nn = 0; nn < 2; nn++) {
            int d = pwn * 16 + nn * 8 + 2 * cq;
            int gcol = h * HDx + d;
            int kb = gcol >> 3, cc = gcol & 7;
            int slot = (cc < 4) ? 0 : 2;
            size_t base_ = ((size_t)mb * 128 + kb) * 32;
            float2 w0 = {tf32f(oc[nn][0] * ia), tf32f(oc[nn][2] * ib)};
            float2 w1 = {tf32f(oc[nn][1] * ia), tf32f(oc[nn][3] * ib)};
            int tt0 = r * 4 + (cc & 3);
            int tt1 = r * 4 + ((cc + 1) & 3);
            *(float2*)&aout[(base_ + tt0) * 4 + slot] = w0;
            *(float2*)&aout[(base_ + tt1) * 4 + slot] = w1;
        }
    }
}

// ---------------------------------------------------------------------------
extern "C" void kernel_launch(void* const* d_in, const int* in_sizes, int n_in,
                              void* d_out, int out_size) {
    const float* x      = (const float*)d_in[0];
    const float* mask   = (const float*)d_in[1];
    const float* w_attn = (const float*)d_in[2];
    const float* b_attn = (const float*)d_in[3];
    const float* w_proj = (const float*)d_in[4];
    const float* b_proj = (const float*)d_in[5];

    float* out_a = (float*)d_out;
    float* out_w = (float*)d_out + (size_t)Bx * Sx * Dx;

    float *qkv, *aout, *xaf, *waf, *wpf, *kTf, *vTf;
    cudaGetSymbolAddress((void**)&qkv,  g_qkv);
    cudaGetSymbolAddress((void**)&aout, g_aout);
    cudaGetSymbolAddress((void**)&xaf,  g_xaf);
    cudaGetSymbolAddress((void**)&waf,  g_waf);
    cudaGetSymbolAddress((void**)&wpf,  g_wpf);
    cudaGetSymbolAddress((void**)&kTf,  g_kTf);
    cudaGetSymbolAddress((void**)&vTf,  g_vTf);

    static const int ATTN_SMEM = 52384 * 4;   // 209536 B
    cudaFuncSetAttribute(attn_mma, cudaFuncAttributeMaxDynamicSharedMemorySize, ATTN_SMEM);
    cudaFuncSetAttribute(gemm_mma, cudaFuncAttributeMaxDynamicSharedMemorySize, GEMM_SMEM);

    // fragment-pack inputs (tf32 rounding fused)
    {
        pack_a<<<(Bx * Sx * Dx / 4) / 256, 256>>>(x, xaf, Dx);
        pack_b<<<(Dx * TDx / 2) / 256, 256>>>(w_attn, waf, Dx, TDx);
        pack_b<<<(Dx * Dx / 2) / 256, 256>>>(w_proj, wpf, Dx, Dx);
    }
    // K1: qkv = x @ w_attn + b_attn
    {
        dim3 grid(TDx / 128, (Bx * Sx) / 128);
        gemm_mma<<<grid, 256, GEMM_SMEM>>>(xaf, waf, b_attn, qkv, Bx * Sx, TDx, Dx);
    }
    // frag-pack K and V
    {
        prep_kTf<<<(Bx * Hx * Sx * HDx / 2) / 256, 256>>>(qkv, kTf);
        prep_vTf<<<(Bx * Hx * Sx * HDx / 2) / 256, 256>>>(qkv, vTf);
    }
    {
        dim3 grid(Sx / 32, Hx, Bx);
        attn_mma<<<grid, 512, ATTN_SMEM>>>(qkv, kTf, vTf, mask, out_w, aout);
    }
    // K3: a = aout @ w_proj + b_proj  (aout already frag-packed by attn)
    {
        dim3 grid(Dx / 128, (Bx * Sx) / 128);
        gemm_mma<<<grid, 256, GEMM_SMEM>>>(aout, wpf, b_proj, out_a, Bx * Sx, Dx, Dx);
    }
}

// round 16
// speedup vs baseline: 1.9002x; 1.0200x over previous
#include <cuda_runtime.h>
#include <cuda.h>
#include <cuda_bf16.h>
#include <cstdint>
#include <math.h>

#define Bx 4
#define Sx 1024
#define Dx 1024
#define Hx 16
#define HDx 64
#define TDx 3072
#define SCS 1028   // scores smem row stride (== 4 mod 32 -> conflict-free frags)

__device__ float g_qkv[Bx * Sx * TDx];       // only Q region (cols<1024) written
__device__ float g_aout[Bx * Sx * Dx];       // K3 A operand, FRAGMENT-PACKED
__device__ float g_xaf[Bx * Sx * Dx];        // x, A-frag packed, tf32
__device__ float g_waf[Dx * TDx];            // w_attn, B-frag packed, tf32
__device__ float g_wpf[Dx * Dx];             // w_proj, B-frag packed, tf32
__device__ float g_kTf[Bx * Hx * Sx * HDx];  // K, B-frag packed [bh][jb][kb][32][2]
__device__ float g_vTf[Bx * Hx * HDx * Sx];  // V, B-frag packed [bh][db][jbk][32][2]

// ---------------------------------------------------------------------------
__device__ __forceinline__ unsigned f2tf32(float f) {
    unsigned r;
    asm("cvt.rna.tf32.f32 %0, %1;" : "=r"(r) : "f"(f));
    return r;
}
__device__ __forceinline__ float tf32f(float f) { return __uint_as_float(f2tf32(f)); }

__device__ __forceinline__ void mma_tf32(float c[4], const unsigned a[4], const unsigned b[2]) {
    asm volatile("mma.sync.aligned.m16n8k8.row.col.f32.tf32.tf32.f32 "
        "{%0,%1,%2,%3}, {%4,%5,%6,%7}, {%8,%9}, {%0,%1,%2,%3};"
        : "+f"(c[0]), "+f"(c[1]), "+f"(c[2]), "+f"(c[3])
        : "r"(a[0]), "r"(a[1]), "r"(a[2]), "r"(a[3]), "r"(b[0]), "r"(b[1]));
}

__device__ __forceinline__ float expapx(float x) {
    float y = fmaxf(x * 1.4426950408889634f, -80.f);
    float t = y + 12582912.f;
    int   n = __float_as_int(t) - 0x4b400000;
    float f = y - (t - 12582912.f);
    float p = 1.3333558146428443e-3f;
    p = fmaf(p, f, 9.618129842118066e-3f);
    p = fmaf(p, f, 5.550410866482158e-2f);
    p = fmaf(p, f, 2.402265069591007e-1f);
    p = fmaf(p, f, 6.931471805599453e-1f);
    p = fmaf(p, f, 1.0f);
    return __int_as_float(__float_as_int(p) + (n << 23));
}

#define CP16(dst, src) asm volatile("cp.async.cg.shared.global [%0], [%1], 16;" :: "r"(dst), "l"(src))
#define CP_COMMIT()    asm volatile("cp.async.commit_group;")
#define CP_WAIT1()     asm volatile("cp.async.wait_group 1;")
#define CP_WAIT0()     asm volatile("cp.async.wait_group 0;")
#define BARP()         asm volatile("bar.sync 1, 256;" ::: "memory")

// ---------------------------------------------------------------------------
// A-frag pack: A[M][K] -> Af[M/16][K/8][32][4] (tf32-rounded)
__global__ void pack_a(const float* __restrict__ A, float* __restrict__ Af, int K) {
    int i = blockIdx.x * 256 + threadIdx.x;
    int KB = K >> 3;
    int tt = i & 31;
    int kb = (i >> 5) % KB;
    int mb = (i >> 5) / KB;
    int r = tt >> 2, cq = tt & 3;
    size_t row = mb * 16 + r, col = kb * 8 + cq;
    uint4 o;
    o.x = f2tf32(A[row * K + col]);
    o.y = f2tf32(A[(row + 8) * K + col]);
    o.z = f2tf32(A[row * K + col + 4]);
    o.w = f2tf32(A[(row + 8) * K + col + 4]);
    *(uint4*)&Af[(size_t)i * 4] = o;
}

// B-frag pack: B[K][N] -> Bf[N/8][K/8][32][2] (tf32-rounded)
__global__ void pack_b(const float* __restrict__ B, float* __restrict__ Bf, int K, int N) {
    int i = blockIdx.x * 256 + threadIdx.x;
    int KB = K >> 3;
    int tt = i & 31;
    int kb = (i >> 5) % KB;
    int nb = (i >> 5) / KB;
    int r = tt >> 2, cq = tt & 3;
    size_t n = nb * 8 + r, k = kb * 8 + cq;
    uint2 o;
    o.x = f2tf32(B[k * N + n]);
    o.y = f2tf32(B[(k + 4) * N + n]);
    *(uint2*)&Bf[(size_t)i * 2] = o;
}

// ---------------------------------------------------------------------------
// tf32 GEMM on fragment-packed operands. fuse=1 (K1): cols>=1024 write K/V
// B-frags to kTf/vTf via warp shuffles; cols<1024 (Q) go to C (qkv).
// fuse=0 (K3): plain row-major store.
// ---------------------------------------------------------------------------
#define GEMM_SMEM 98304
__global__ __launch_bounds__(256, 2) void gemm_mma(const float* __restrict__ Af,
                                                   const float* __restrict__ Bf,
                                                   const float* __restrict__ bias,
                                                   float* __restrict__ C,
                                                   float* __restrict__ kTf,
                                                   float* __restrict__ vTf,
                                                   int M, int N, int K, int fuse) {
    extern __shared__ float gsm[];
    float* Asb = gsm;
    float* Bsb = gsm + 3 * 4096;

    const int t = threadIdx.x;
    const int warp = t >> 5, lane = t & 31;
    const int wm = warp >> 2, wn = warp & 3;
    const int r = lane >> 2, cq = lane & 3;
    const int row0 = blockIdx.y * 128, col0 = blockIdx.x * 128;
    const int rowb0 = row0 >> 4, colb0 = col0 >> 3;
    const int KB = K >> 3;

    float acc[4][4][4];
    #pragma unroll
    for (int i = 0; i < 4; i++)
        #pragma unroll
        for (int j = 0; j < 4; j++)
            #pragma unroll
            for (int k = 0; k < 4; k++) acc[i][j][k] = 0.f;

    auto loadG = [&](int st, int kb0) {
        float* As = Asb + st * 4096;
        float* Bs = Bsb + st * 4096;
        #pragma unroll
        for (int i = 0; i < 4; i++) {
            int id = t + i * 256;
            int mb = id >> 7, remA = id & 127, kbA = remA >> 5, cA = remA & 31;
            unsigned da = (unsigned)__cvta_generic_to_shared(&As[(mb * 4 + kbA) * 128 + cA * 4]);
            CP16(da, &Af[((size_t)(rowb0 + mb) * KB + kb0 + kbA) * 128 + cA * 4]);
            int nb = id >> 6, remB = id & 63, kbB = remB >> 4, cB = remB & 15;
            unsigned db = (unsigned)__cvta_generic_to_shared(&Bs[(nb * 4 + kbB) * 64 + cB * 4]);
            CP16(db, &Bf[((size_t)(colb0 + nb) * KB + kb0 + kbB) * 64 + cB * 4]);
        }
    };

    loadG(0, 0); CP_COMMIT();
    loadG(1, 4); CP_COMMIT();

    const int NT = K / 32;
    int st = 0;
    for (int kt = 0; kt < NT; kt++) {
        if (kt + 1 < NT) CP_WAIT1(); else CP_WAIT0();
        __syncthreads();
        if (kt + 2 < NT) {
            int st2 = st + 2; if (st2 >= 3) st2 -= 3;
            loadG(st2, (kt + 2) * 4);
            CP_COMMIT();
        }
        const float* As = Asb + st * 4096;
        const float* Bs = Bsb + st * 4096;

        #pragma unroll
        for (int kb = 0; kb < 4; kb++) {
            unsigned a[4][4], b[4][2];
            #pragma unroll
            for (int mm = 0; mm < 4; mm++) {
                uint4 v = *(const uint4*)&As[((wm * 4 + mm) * 4 + kb) * 128 + lane * 4];
                a[mm][0] = v.x; a[mm][1] = v.y; a[mm][2] = v.z; a[mm][3] = v.w;
            }
            #pragma unroll
            for (int nn = 0; nn < 4; nn++) {
                uint2 v = *(const uint2*)&Bs[((wn * 4 + nn) * 4 + kb) * 64 + lane * 2];
                b[nn][0] = v.x; b[nn][1] = v.y;
            }
            #pragma unroll
            for (int mm = 0; mm < 4; mm++)
                #pragma unroll
                for (int nn = 0; nn < 4; nn++)
                    mma_tf32(acc[mm][nn], a[mm], b[nn]);
        }
        if (++st == 3) st = 0;
    }

    const int region = (fuse == 0) ? 0 : (col0 >= 2048 ? 2 : (col0 >= 1024 ? 1 : 0));

    #pragma unroll
    for (int mm = 0; mm < 4; mm++) {
        int r0 = row0 + wm * 64 + mm * 16 + r;
        int tokBase = (r0 - r) & 1023;     // 16-aligned token base
        int bb = (r0 - r) >> 10;
        #pragma unroll
        for (int nn = 0; nn < 4; nn++) {
            int C0 = col0 + wn * 32 + nn * 8;
            int c0 = C0 + 2 * cq;
            float2 bv = *(const float2*)&bias[c0];
            float v0 = acc[mm][nn][0] + bv.x;
            float v1 = acc[mm][nn][1] + bv.y;
            float v2 = acc[mm][nn][2] + bv.x;
            float v3 = acc[mm][nn][3] + bv.y;
            if (region == 0) {
                float2 o0 = {v0, v1};
                float2 o1 = {v2, v3};
                *(float2*)&C[(size_t)r0 * N + c0] = o0;
                *(float2*)&C[(size_t)(r0 + 8) * N + c0] = o1;
            } else if (region == 1) {
                // K: dest lane (r,cq): b0 <- col cq, b1 <- col cq+4 of its row
                int srcA = (lane & ~3) | (cq >> 1);
                int srcB = srcA + 2;
                float a0A = __shfl_sync(0xffffffffu, v0, srcA);
                float a1A = __shfl_sync(0xffffffffu, v1, srcA);
                float a0B = __shfl_sync(0xffffffffu, v0, srcB);
                float a1B = __shfl_sync(0xffffffffu, v1, srcB);
                float a2A = __shfl_sync(0xffffffffu, v2, srcA);
                float a3A = __shfl_sync(0xffffffffu, v3, srcA);
                float a2B = __shfl_sync(0xffffffffu, v2, srcB);
                float a3B = __shfl_sync(0xffffffffu, v3, srcB);
                bool odd = (cq & 1);
                uint2 o0 = {f2tf32(odd ? a1A : a0A), f2tf32(odd ? a1B : a0B)};  // jb0
                uint2 o1 = {f2tf32(odd ? a3A : a0B * 0.f + (odd ? a3A : a2A)), 0u};
                // (compute o1 cleanly below)
                float b0j1 = odd ? a3A : a2A;
                float b1j1 = odd ? a3B : a2B;
                o1.x = f2tf32(b0j1); o1.y = f2tf32(b1j1);
                int c = C0 - 1024;
                int h = c >> 6, kb = (c & 63) >> 3;
                size_t base_ = (((size_t)(bb * Hx + h) * 128 + (tokBase >> 3)) * 8 + kb) * 64;
                *(uint2*)&kTf[base_ + lane * 2] = o0;
                *(uint2*)&kTf[base_ + 512 + lane * 2] = o1;     // jb+1
            } else {
                // V: dest lane (r,cq): b0 = (j=cq, d=r), b1 = (j=cq+4, d=r)
                int lA = cq * 4 + (r >> 1);
                int lB = lA + 16;
                float s0A = __shfl_sync(0xffffffffu, v0, lA);
                float s1A = __shfl_sync(0xffffffffu, v1, lA);
                float s0B = __shfl_sync(0xffffffffu, v0, lB);
                float s1B = __shfl_sync(0xffffffffu, v1, lB);
                float s2A = __shfl_sync(0xffffffffu, v2, lA);
                float s3A = __shfl_sync(0xffffffffu, v3, lA);
                float s2B = __shfl_sync(0xffffffffu, v2, lB);
                float s3B = __shfl_sync(0xffffffffu, v3, lB);
                bool odd = (r & 1);
                uint2 o0 = {f2tf32(odd ? s1A : s0A), f2tf32(odd ? s1B : s0B)};  // jbk0
                uint2 o1 = {f2tf32(odd ? s3A : s2A), f2tf32(odd ? s3B : s2B)};  // jbk1
                int c = C0 - 2048;
                int h = c >> 6, db = (c & 63) >> 3;
                size_t base_ = (((size_t)(bb * Hx + h) * 8 + db) * 128 + (tokBase >> 3)) * 64;
                *(uint2*)&vTf[base_ + lane * 2] = o0;
                *(uint2*)&vTf[base_ + 64 + lane * 2] = o1;      // jbk+1
            }
        }
    }
}

// ---------------------------------------------------------------------------
// Tensor-core attention, 512 threads, fragment-packed K/V/Q operands.
// Rowsum by all warps, then warps 0-7 w-store || warps 8-15 PV.
// ---------------------------------------------------------------------------
__global__ __launch_bounds__(512) void attn_mma(const float* __restrict__ qkv,
                                                const float* __restrict__ kTf,
                                                const float* __restrict__ vTf,
                                                const float* __restrict__ mask,
                                                float* __restrict__ w_out,
                                                float* __restrict__ aout) {
    extern __shared__ float sm[];
    float* sc   = sm;
    float* qsf  = sm + 32896;
    float* kvb  = sm + 34944;
    float* mks  = sm + 51328;
    float* invs = sm + 52352;

    const int q0 = (Sx / 32 - 1 - blockIdx.x) * 32;   // biggest work first
    const int h  = blockIdx.y;
    const int b  = blockIdx.z;
    const int bh = b * Hx + h;
    const int t  = threadIdx.x;
    const int warp = t >> 5, lane = t & 31;
    const int r = lane >> 2, cq = lane & 3;
    const int wm = warp >> 3;
    const int wn = warp & 7;
    const float* base = qkv + (size_t)b * Sx * TDx;
    const float* kTfb = kTf + (size_t)bh * Sx * HDx;
    const float* vTfb = vTf + (size_t)bh * HDx * Sx;

    auto stageK = [&](int buf, int jt) {
        float* dstb = kvb + buf * 8192;
        const float* src = kTfb + (size_t)jt * 8192;
        #pragma unroll
        for (int i = 0; i < 4; i++) {
            int id = t + i * 512;
            unsigned d = (unsigned)__cvta_generic_to_shared(&dstb[id * 4]);
            CP16(d, &src[id * 4]);
        }
    };
    auto stageV = [&](int buf, int jt) {
        float* dstb = kvb + buf * 8192;
        int t2 = t - 256;
        #pragma unroll
        for (int i = 0; i < 8; i++) {
            int id = t2 + i * 256;
            int db = id >> 8, rem = id & 255;
            unsigned d = (unsigned)__cvta_generic_to_shared(&dstb[(db * 256 + rem) * 4]);
            CP16(d, &vTfb[(size_t)db * 8192 + (size_t)jt * 1024 + rem * 4]);
        }
    };

    if (t < 256) *(float4*)&mks[4 * t] = *(const float4*)&mask[b * Sx + 4 * t];
    {
        int g = t >> 5, tt = t & 31;
        int mbq = g >> 3, kbq = g & 7;
        int rr = tt >> 2, cc = tt & 3;
        const float* q0p = &base[(size_t)(q0 + mbq * 16 + rr) * TDx + h * HDx + kbq * 8 + cc];
        const float* q1p = q0p + 8 * TDx;
        uint4 qa;
        qa.x = f2tf32(q0p[0]); qa.y = f2tf32(q1p[0]);
        qa.z = f2tf32(q0p[4]); qa.w = f2tf32(q1p[4]);
        *(uint4*)&qsf[g * 128 + tt * 4] = qa;
    }

    const int ntile = (q0 + 31) / 128 + 1;
    const int Ccols = ntile * 128;

    stageK(0, 0);
    CP_COMMIT();
    __syncthreads();

    // ---- scores ----
    for (int jt = 0; jt < ntile; jt++) {
        const int j0 = jt * 128;
        if (jt + 1 < ntile) { stageK((jt + 1) & 1, jt + 1); CP_COMMIT(); CP_WAIT1(); }
        else                { CP_WAIT0(); }
        __syncthreads();
        const float* kst = kvb + (jt & 1) * 8192;

        float c[2][4];
        #pragma unroll
        for (int i = 0; i < 2; i++)
            #pragma unroll
            for (int j = 0; j < 4; j++) c[i][j] = 0.f;

        #pragma unroll
        for (int ks = 0; ks < 8; ks++) {
            unsigned a[4];
            uint4 av = *(const uint4*)&qsf[(wm * 8 + ks) * 128 + lane * 4];
            a[0] = av.x; a[1] = av.y; a[2] = av.z; a[3] = av.w;
            #pragma unroll
            for (int nn = 0; nn < 2; nn++) {
                uint2 bv = *(const uint2*)&kst[((wn * 2 + nn) * 8 + ks) * 64 + lane * 2];
                unsigned bf[2] = {bv.x, bv.y};
                mma_tf32(c[nn], a, bf);
            }
        }

        const int qa_ = q0 + wm * 16 + r;
        const int qb_ = qa_ + 8;
        #pragma unroll
        for (int nn = 0; nn < 2; nn++) {
            int jl = wn * 16 + nn * 8 + 2 * cq;
            int jg = j0 + jl;
            float mk0 = mks[jg], mk1 = mks[jg + 1];
            float* s0 = &sc[(wm * 16 + r) * SCS + jg];
            float* s1 = &sc[(wm * 16 + r + 8) * SCS + jg];
            s0[0] = (jg     <= qa_) ? tf32f(expapx(fmaf(c[nn][0], 0.125f, mk0))) : 0.f;
            s0[1] = (jg + 1 <= qa_) ? tf32f(expapx(fmaf(c[nn][1], 0.125f, mk1))) : 0.f;
            s1[0] = (jg     <= qb_) ? tf32f(expapx(fmaf(c[nn][2], 0.125f, mk0))) : 0.f;
            s1[1] = (jg + 1 <= qb_) ? tf32f(expapx(fmaf(c[nn][3], 0.125f, mk1))) : 0.f;
        }
        __syncthreads();
    }
    // sc complete. PV warps kick off V prefetch, then ALL warps rowsum.
    if (warp >= 8) { stageV(0, 0); CP_COMMIT(); }

    #pragma unroll
    for (int rr = 0; rr < 2; rr++) {
        int row = warp * 2 + rr;
        float s = 0.f;
        for (int j4 = lane * 4; j4 < Ccols; j4 += 128) {
            float4 v = *(float4*)&sc[row * SCS + j4];
            s += v.x + v.y + v.z + v.w;
        }
        #pragma unroll
        for (int o = 16; o > 0; o >>= 1) s += __shfl_xor_sync(0xffffffffu, s, o);
        if (lane == 0) invs[row] = 1.f / s;
    }
    __syncthreads();

    float oc[2][4];
    #pragma unroll
    for (int i = 0; i < 2; i++)
        #pragma unroll
        for (int j = 0; j < 4; j++) oc[i][j] = 0.f;

    if (warp < 8) {
        // ---- w-store half: normalized store + zero fill ----
        #pragma unroll
        for (int rr = 0; rr < 4; rr++) {
            int row = warp * 4 + rr;
            float inv = invs[row];
            size_t wb = ((size_t)(bh * Sx + q0 + row)) * Sx;
            for (int j4 = lane * 4; j4 < Ccols; j4 += 128) {
                float4 v = *(float4*)&sc[row * SCS + j4];
                float4 o4 = {v.x * inv, v.y * inv, v.z * inv, v.w * inv};
                *(float4*)&w_out[wb + j4] = o4;
            }
            float4 z = {0.f, 0.f, 0.f, 0.f};
            for (int j4 = Ccols + lane * 4; j4 < Sx; j4 += 128)
                *(float4*)&w_out[wb + j4] = z;
        }
    } else {
        // ---- PV half: 8 warps, 2(M) x 4(N of 16 cols) ----
        const int pwm = (warp - 8) >> 2;
        const int pwn = (warp - 8) & 3;

        for (int jt = 0; jt < ntile; jt++) {
            const int j0 = jt * 128;
            if (jt + 1 < ntile) { stageV((jt + 1) & 1, jt + 1); CP_COMMIT(); CP_WAIT1(); }
            else                { CP_WAIT0(); }
            BARP();
            const float* vst = kvb + (jt & 1) * 8192;

            #pragma unroll
            for (int ks = 0; ks < 16; ks++) {
                const int kb = ks * 8;
                unsigned a[4];
                const float* ap0 = &sc[(pwm * 16 + r) * SCS + j0 + kb + cq];
                const float* ap1 = ap0 + 8 * SCS;
                a[0] = __float_as_uint(ap0[0]);
                a[1] = __float_as_uint(ap1[0]);
                a[2] = __float_as_uint(ap0[4]);
                a[3] = __float_as_uint(ap1[4]);
                #pragma unroll
                for (int nn = 0; nn < 2; nn++) {
                    uint2 bv = *(const uint2*)&vst[((pwn * 2 + nn) * 16 + ks) * 64 + lane * 2];
                    unsigned bf[2] = {bv.x, bv.y};
                    mma_tf32(oc[nn], a, bf);
                }
            }
            BARP();
        }
    }
    __syncthreads();

    if (warp >= 8) {
        const int pwm = (warp - 8) >> 2;
        const int pwn = (warp - 8) & 3;
        float ia = invs[pwm * 16 + r], ib = invs[pwm * 16 + r + 8];
        int mb = ((b * Sx + q0) >> 4) + pwm;
        #pragma unroll
        for (int nn = 0; nn < 2; nn++) {
            int d = pwn * 16 + nn * 8 + 2 * cq;
            int gcol = h * HDx + d;
            int kb = gcol >> 3, cc = gcol & 7;
            int slot = (cc < 4) ? 0 : 2;
            size_t base_ = ((size_t)mb * 128 + kb) * 32;
            float2 w0 = {tf32f(oc[nn][0] * ia), tf32f(oc[nn][2] * ib)};
            float2 w1 = {tf32f(oc[nn][1] * ia), tf32f(oc[nn][3] * ib)};
            int tt0 = r * 4 + (cc & 3);
            int tt1 = r * 4 + ((cc + 1) & 3);
            *(float2*)&aout[(base_ + tt0) * 4 + slot] = w0;
            *(float2*)&aout[(base_ + tt1) * 4 + slot] = w1;
        }
    }
}

// ---------------------------------------------------------------------------
extern "C" void kernel_launch(void* const* d_in, const int* in_sizes, int n_in,
                              void* d_out, int out_size) {
    const float* x      = (const float*)d_in[0];
    const float* mask   = (const float*)d_in[1];
    const float* w_attn = (const float*)d_in[2];
    const float* b_attn = (const float*)d_in[3];
    const float* w_proj = (const float*)d_in[4];
    const float* b_proj = (const float*)d_in[5];

    float* out_a = (float*)d_out;
    float* out_w = (float*)d_out + (size_t)Bx * Sx * Dx;

    float *qkv, *aout, *xaf, *waf, *wpf, *kTf, *vTf;
    cudaGetSymbolAddress((void**)&qkv,  g_qkv);
    cudaGetSymbolAddress((void**)&aout, g_aout);
    cudaGetSymbolAddress((void**)&xaf,  g_xaf);
    cudaGetSymbolAddress((void**)&waf,  g_waf);
    cudaGetSymbolAddress((void**)&wpf,  g_wpf);
    cudaGetSymbolAddress((void**)&kTf,  g_kTf);
    cudaGetSymbolAddress((void**)&vTf,  g_vTf);

    static const int ATTN_SMEM = 52384 * 4;   // 209536 B
    cudaFuncSetAttribute(attn_mma, cudaFuncAttributeMaxDynamicSharedMemorySize, ATTN_SMEM);
    cudaFuncSetAttribute(gemm_mma, cudaFuncAttributeMaxDynamicSharedMemorySize, GEMM_SMEM);

    {
        pack_a<<<(Bx * Sx * Dx / 4) / 256, 256>>>(x, xaf, Dx);
        pack_b<<<(Dx * TDx / 2) / 256, 256>>>(w_attn, waf, Dx, TDx);
        pack_b<<<(Dx * Dx / 2) / 256, 256>>>(w_proj, wpf, Dx, Dx);
    }
    // K1: qkv = x @ w_attn + b_attn ; K/V fused out as B-frags
    {
        dim3 grid(TDx / 128, (Bx * Sx) / 128);
        gemm_mma<<<grid, 256, GEMM_SMEM>>>(xaf, waf, b_attn, qkv, kTf, vTf,
                                           Bx * Sx, TDx, Dx, 1);
    }
    {
        dim3 grid(Sx / 32, Hx, Bx);
        attn_mma<<<grid, 512, ATTN_SMEM>>>(qkv, kTf, vTf, mask, out_w, aout);
    }
    // K3: a = aout @ w_proj + b_proj  (aout already frag-packed by attn)
    {
        dim3 grid(Dx / 128, (Bx * Sx) / 128);
        gemm_mma<<<grid, 256, GEMM_SMEM>>>(aout, wpf, b_proj, out_a, kTf, vTf,
                                           Bx * Sx, Dx, Dx, 0);
    }
}

// round 17
// speedup vs baseline: 2.4303x; 1.2790x over previous
#include <cuda_runtime.h>
#include <cuda.h>
#include <cuda_fp16.h>
#include <cstdint>
#include <math.h>

#define Bx 4
#define Sx 1024
#define Dx 1024
#define Hx 16
#define HDx 64
#define TDx 3072
#define SCS 1028   // scores smem row stride (== 4 mod 32 -> conflict-free frags)

__device__ float    g_qkv[Bx * Sx * TDx];        // f32 QKV (K1 output)
__device__ unsigned g_aoutH[Bx * Sx * Dx / 2];   // attn out, fp16 A-frag packed
__device__ unsigned g_xah[Bx * Sx * Dx / 2];     // x, fp16 A-frag packed
__device__ unsigned g_wah[Dx * TDx / 2];         // w_attn, fp16 B-frag packed
__device__ unsigned g_wph[Dx * Dx / 2];          // w_proj, fp16 B-frag packed
__device__ float    g_kTf[Bx * Hx * Sx * HDx];   // K, tf32 B-frag [bh][jb][kb][32][2]
__device__ float    g_vTf[Bx * Hx * HDx * Sx];   // V, tf32 B-frag [bh][db][jbk][32][2]

// ---------------------------------------------------------------------------
__device__ __forceinline__ unsigned f2tf32(float f) {
    unsigned r;
    asm("cvt.rna.tf32.f32 %0, %1;" : "=r"(r) : "f"(f));
    return r;
}
__device__ __forceinline__ float tf32f(float f) { return __uint_as_float(f2tf32(f)); }
__device__ __forceinline__ unsigned pk(float lo, float hi) {
    __half2 h = __floats2half2_rn(lo, hi);
    return *(unsigned*)&h;
}

__device__ __forceinline__ void mma_tf32(float c[4], const unsigned a[4], const unsigned b[2]) {
    asm volatile("mma.sync.aligned.m16n8k8.row.col.f32.tf32.tf32.f32 "
        "{%0,%1,%2,%3}, {%4,%5,%6,%7}, {%8,%9}, {%0,%1,%2,%3};"
        : "+f"(c[0]), "+f"(c[1]), "+f"(c[2]), "+f"(c[3])
        : "r"(a[0]), "r"(a[1]), "r"(a[2]), "r"(a[3]), "r"(b[0]), "r"(b[1]));
}
__device__ __forceinline__ void mma_f16(float c[4], const unsigned a[4], const unsigned b[2]) {
    asm volatile("mma.sync.aligned.m16n8k16.row.col.f32.f16.f16.f32 "
        "{%0,%1,%2,%3}, {%4,%5,%6,%7}, {%8,%9}, {%0,%1,%2,%3};"
        : "+f"(c[0]), "+f"(c[1]), "+f"(c[2]), "+f"(c[3])
        : "r"(a[0]), "r"(a[1]), "r"(a[2]), "r"(a[3]), "r"(b[0]), "r"(b[1]));
}

__device__ __forceinline__ float expapx(float x) {
    float y = fmaxf(x * 1.4426950408889634f, -80.f);
    float t = y + 12582912.f;
    int   n = __float_as_int(t) - 0x4b400000;
    float f = y - (t - 12582912.f);
    float p = 1.3333558146428443e-3f;
    p = fmaf(p, f, 9.618129842118066e-3f);
    p = fmaf(p, f, 5.550410866482158e-2f);
    p = fmaf(p, f, 2.402265069591007e-1f);
    p = fmaf(p, f, 6.931471805599453e-1f);
    p = fmaf(p, f, 1.0f);
    return __int_as_float(__float_as_int(p) + (n << 23));
}

#define CP16(dst, src) asm volatile("cp.async.cg.shared.global [%0], [%1], 16;" :: "r"(dst), "l"(src))
#define CP_COMMIT()    asm volatile("cp.async.commit_group;")
#define CP_WAIT1()     asm volatile("cp.async.wait_group 1;")
#define CP_WAIT0()     asm volatile("cp.async.wait_group 0;")
#define BARP()         asm volatile("bar.sync 1, 256;" ::: "memory")

// ---------------------------------------------------------------------------
// fp16 A-frag pack: A[M][K] f32 -> Ah[M/16][K/16][32][4 u32]
__global__ void pack_a_h(const float* __restrict__ A, unsigned* __restrict__ Ah, int K) {
    int i = blockIdx.x * 256 + threadIdx.x;
    int KB16 = K >> 4;
    int tt = i & 31;
    int kb = (i >> 5) % KB16;
    int mb = (i >> 5) / KB16;
    int r = tt >> 2, cq = tt & 3;
    size_t row = mb * 16 + r, col = kb * 16 + 2 * cq;
    uint4 o;
    o.x = pk(A[row * K + col],           A[row * K + col + 1]);
    o.y = pk(A[(row + 8) * K + col],     A[(row + 8) * K + col + 1]);
    o.z = pk(A[row * K + col + 8],       A[row * K + col + 9]);
    o.w = pk(A[(row + 8) * K + col + 8], A[(row + 8) * K + col + 9]);
    ((uint4*)Ah)[i] = o;
}

// fp16 B-frag pack: B[K][N] f32 -> Bh[N/8][K/16][32][2 u32]
__global__ void pack_b_h(const float* __restrict__ B, unsigned* __restrict__ Bh, int K, int N) {
    int i = blockIdx.x * 256 + threadIdx.x;
    int KB16 = K >> 4;
    int tt = i & 31;
    int kb = (i >> 5) % KB16;
    int nb = (i >> 5) / KB16;
    int r = tt >> 2, cq = tt & 3;
    size_t n = nb * 8 + r, k = kb * 16 + 2 * cq;
    uint2 o;
    o.x = pk(B[k * N + n],       B[(k + 1) * N + n]);
    o.y = pk(B[(k + 8) * N + n], B[(k + 9) * N + n]);
    ((uint2*)Bh)[i] = o;
}

// K tf32 B-frag pack: kTf[bh][jb(128)][kb(8)][32][2]
__global__ void prep_kTf(const float* __restrict__ qkv, float* __restrict__ kTf) {
    int i = blockIdx.x * 256 + threadIdx.x;
    int tt = i & 31;
    int kb = (i >> 5) & 7;
    int jb = (i >> 8) & 127;
    int bh = i >> 15;
    int b = bh >> 4, h = bh & 15;
    int r = tt >> 2, cq = tt & 3;
    const float* src = &qkv[((size_t)(b * Sx + jb * 8 + r)) * TDx + Dx + h * HDx + kb * 8 + cq];
    uint2 o = {f2tf32(src[0]), f2tf32(src[4])};
    *(uint2*)&kTf[(size_t)i * 2] = o;
}

// V tf32 B-frag pack: vTf[bh][db(8)][jbk(128)][32][2]
__global__ void prep_vTf(const float* __restrict__ qkv, float* __restrict__ vTf) {
    int i = blockIdx.x * 256 + threadIdx.x;
    int tt = i & 31;
    int jbk = (i >> 5) & 127;
    int db = (i >> 12) & 7;
    int bh = i >> 15;
    int b = bh >> 4, h = bh & 15;
    int r = tt >> 2, cq = tt & 3;
    const float* src = &qkv[((size_t)(b * Sx + jbk * 8 + cq)) * TDx + 2 * Dx + h * HDx + db * 8 + r];
    uint2 o = {f2tf32(src[0]), f2tf32(src[4 * TDx])};
    *(uint2*)&vTf[(size_t)i * 2] = o;
}

// ---------------------------------------------------------------------------
// fp16 m16n8k16 GEMM on fragment-packed operands. CTA 128x128, k-tile 32
// (2 kb16 blocks), 3-stage cp.async. Stage = 16KB; 3 stages = 48KB.
// ---------------------------------------------------------------------------
#define GEMM_SMEM 49152
__global__ __launch_bounds__(256, 2) void gemm_h(const unsigned* __restrict__ Ah,
                                                 const unsigned* __restrict__ Bh,
                                                 const float* __restrict__ bias,
                                                 float* __restrict__ C,
                                                 int M, int N, int K) {
    extern __shared__ unsigned hsm[];

    const int t = threadIdx.x;
    const int warp = t >> 5, lane = t & 31;
    const int wm = warp >> 2, wn = warp & 3;
    const int r = lane >> 2, cq = lane & 3;
    const int row0 = blockIdx.y * 128, col0 = blockIdx.x * 128;
    const int rowb0 = row0 >> 4, colb0 = col0 >> 3;
    const int KB16 = K >> 4;

    float acc[4][4][4];
    #pragma unroll
    for (int i = 0; i < 4; i++)
        #pragma unroll
        for (int j = 0; j < 4; j++)
            #pragma unroll
            for (int k = 0; k < 4; k++) acc[i][j][k] = 0.f;

    // stage: A [8 mb][2 kb][32][4] = 2048 u32 ; B [16 nb][2 kb][32][2] = 2048 u32
    auto loadG = [&](int st, int kb0) {
        unsigned* As = hsm + st * 4096;
        unsigned* Bs = As + 2048;
        #pragma unroll
        for (int i = 0; i < 2; i++) {
            int id = t + i * 256;                       // 0..511
            int mb = id >> 6, remA = id & 63, kbA = remA >> 5, cA = remA & 31;
            unsigned da = (unsigned)__cvta_generic_to_shared(&As[(mb * 2 + kbA) * 128 + cA * 4]);
            CP16(da, &Ah[((size_t)(rowb0 + mb) * KB16 + kb0 + kbA) * 128 + cA * 4]);
            int nb = id >> 5, remB = id & 31, kbB = remB >> 4, cB = remB & 15;
            unsigned db = (unsigned)__cvta_generic_to_shared(&Bs[(nb * 2 + kbB) * 64 + cB * 4]);
            CP16(db, &Bh[((size_t)(colb0 + nb) * KB16 + kb0 + kbB) * 64 + cB * 4]);
        }
    };

    loadG(0, 0); CP_COMMIT();
    loadG(1, 2); CP_COMMIT();

    const int NT = K / 32;
    int st = 0;
    for (int kt = 0; kt < NT; kt++) {
        if (kt + 1 < NT) CP_WAIT1(); else CP_WAIT0();
        __syncthreads();
        if (kt + 2 < NT) {
            int st2 = st + 2; if (st2 >= 3) st2 -= 3;
            loadG(st2, (kt + 2) * 2);
            CP_COMMIT();
        }
        const unsigned* As = hsm + st * 4096;
        const unsigned* Bs = As + 2048;

        #pragma unroll
        for (int kb = 0; kb < 2; kb++) {
            unsigned a[4][4], b[4][2];
            #pragma unroll
            for (int mm = 0; mm < 4; mm++) {
                uint4 v = *(const uint4*)&As[((wm * 4 + mm) * 2 + kb) * 128 + lane * 4];
                a[mm][0] = v.x; a[mm][1] = v.y; a[mm][2] = v.z; a[mm][3] = v.w;
            }
            #pragma unroll
            for (int nn = 0; nn < 4; nn++) {
                uint2 v = *(const uint2*)&Bs[((wn * 4 + nn) * 2 + kb) * 64 + lane * 2];
                b[nn][0] = v.x; b[nn][1] = v.y;
            }
            #pragma unroll
            for (int mm = 0; mm < 4; mm++)
                #pragma unroll
                for (int nn = 0; nn < 4; nn++)
                    mma_f16(acc[mm][nn], a[mm], b[nn]);
        }
        if (++st == 3) st = 0;
    }

    #pragma unroll
    for (int mm = 0; mm < 4; mm++) {
        int r0 = row0 + wm * 64 + mm * 16 + r;
        #pragma unroll
        for (int nn = 0; nn < 4; nn++) {
            int c0 = col0 + wn * 32 + nn * 8 + 2 * cq;
            float2 bv = *(const float2*)&bias[c0];
            float2 o0 = {acc[mm][nn][0] + bv.x, acc[mm][nn][1] + bv.y};
            float2 o1 = {acc[mm][nn][2] + bv.x, acc[mm][nn][3] + bv.y};
            *(float2*)&C[(size_t)r0 * N + c0] = o0;
            *(float2*)&C[(size_t)(r0 + 8) * N + c0] = o1;
        }
    }
}

// ---------------------------------------------------------------------------
// Tensor-core attention (tf32, unchanged structure): rowsum by all warps,
// warps 0-7 w-store || warps 8-15 PV. Epilogue writes fp16 A-frags for K3.
// ---------------------------------------------------------------------------
__global__ __launch_bounds__(512) void attn_mma(const float* __restrict__ qkv,
                                                const float* __restrict__ kTf,
                                                const float* __restrict__ vTf,
                                                const float* __restrict__ mask,
                                                float* __restrict__ w_out,
                                                unsigned* __restrict__ aoutH) {
    extern __shared__ float sm[];
    float* sc   = sm;
    float* qsf  = sm + 32896;
    float* kvb  = sm + 34944;
    float* mks  = sm + 51328;
    float* invs = sm + 52352;

    const int q0 = (Sx / 32 - 1 - blockIdx.x) * 32;   // biggest work first
    const int h  = blockIdx.y;
    const int b  = blockIdx.z;
    const int bh = b * Hx + h;
    const int t  = threadIdx.x;
    const int warp = t >> 5, lane = t & 31;
    const int r = lane >> 2, cq = lane & 3;
    const int wm = warp >> 3;
    const int wn = warp & 7;
    const float* base = qkv + (size_t)b * Sx * TDx;
    const float* kTfb = kTf + (size_t)bh * Sx * HDx;
    const float* vTfb = vTf + (size_t)bh * HDx * Sx;

    auto stageK = [&](int buf, int jt) {
        float* dstb = kvb + buf * 8192;
        const float* src = kTfb + (size_t)jt * 8192;
        #pragma unroll
        for (int i = 0; i < 4; i++) {
            int id = t + i * 512;
            unsigned d = (unsigned)__cvta_generic_to_shared(&dstb[id * 4]);
            CP16(d, &src[id * 4]);
        }
    };
    auto stageV = [&](int buf, int jt) {
        float* dstb = kvb + buf * 8192;
        int t2 = t - 256;
        #pragma unroll
        for (int i = 0; i < 8; i++) {
            int id = t2 + i * 256;
            int db = id >> 8, rem = id & 255;
            unsigned d = (unsigned)__cvta_generic_to_shared(&dstb[(db * 256 + rem) * 4]);
            CP16(d, &vTfb[(size_t)db * 8192 + (size_t)jt * 1024 + rem * 4]);
        }
    };

    if (t < 256) *(float4*)&mks[4 * t] = *(const float4*)&mask[b * Sx + 4 * t];
    {
        int g = t >> 5, tt = t & 31;
        int mbq = g >> 3, kbq = g & 7;
        int rr = tt >> 2, cc = tt & 3;
        const float* q0p = &base[(size_t)(q0 + mbq * 16 + rr) * TDx + h * HDx + kbq * 8 + cc];
        const float* q1p = q0p + 8 * TDx;
        uint4 qa;
        qa.x = f2tf32(q0p[0]); qa.y = f2tf32(q1p[0]);
        qa.z = f2tf32(q0p[4]); qa.w = f2tf32(q1p[4]);
        *(uint4*)&qsf[g * 128 + tt * 4] = qa;
    }

    const int ntile = (q0 + 31) / 128 + 1;
    const int Ccols = ntile * 128;

    stageK(0, 0);
    CP_COMMIT();
    __syncthreads();

    // ---- scores ----
    for (int jt = 0; jt < ntile; jt++) {
        const int j0 = jt * 128;
        if (jt + 1 < ntile) { stageK((jt + 1) & 1, jt + 1); CP_COMMIT(); CP_WAIT1(); }
        else                { CP_WAIT0(); }
        __syncthreads();
        const float* kst = kvb + (jt & 1) * 8192;

        float c[2][4];
        #pragma unroll
        for (int i = 0; i < 2; i++)
            #pragma unroll
            for (int j = 0; j < 4; j++) c[i][j] = 0.f;

        #pragma unroll
        for (int ks = 0; ks < 8; ks++) {
            unsigned a[4];
            uint4 av = *(const uint4*)&qsf[(wm * 8 + ks) * 128 + lane * 4];
            a[0] = av.x; a[1] = av.y; a[2] = av.z; a[3] = av.w;
            #pragma unroll
            for (int nn = 0; nn < 2; nn++) {
                uint2 bv = *(const uint2*)&kst[((wn * 2 + nn) * 8 + ks) * 64 + lane * 2];
                unsigned bf[2] = {bv.x, bv.y};
                mma_tf32(c[nn], a, bf);
            }
        }

        const int qa_ = q0 + wm * 16 + r;
        const int qb_ = qa_ + 8;
        #pragma unroll
        for (int nn = 0; nn < 2; nn++) {
            int jl = wn * 16 + nn * 8 + 2 * cq;
            int jg = j0 + jl;
            float mk0 = mks[jg], mk1 = mks[jg + 1];
            float* s0 = &sc[(wm * 16 + r) * SCS + jg];
            float* s1 = &sc[(wm * 16 + r + 8) * SCS + jg];
            s0[0] = (jg     <= qa_) ? tf32f(expapx(fmaf(c[nn][0], 0.125f, mk0))) : 0.f;
            s0[1] = (jg + 1 <= qa_) ? tf32f(expapx(fmaf(c[nn][1], 0.125f, mk1))) : 0.f;
            s1[0] = (jg     <= qb_) ? tf32f(expapx(fmaf(c[nn][2], 0.125f, mk0))) : 0.f;
            s1[1] = (jg + 1 <= qb_) ? tf32f(expapx(fmaf(c[nn][3], 0.125f, mk1))) : 0.f;
        }
        __syncthreads();
    }
    // sc complete. PV warps kick off V prefetch, then ALL warps rowsum.
    if (warp >= 8) { stageV(0, 0); CP_COMMIT(); }

    #pragma unroll
    for (int rr = 0; rr < 2; rr++) {
        int row = warp * 2 + rr;
        float s = 0.f;
        for (int j4 = lane * 4; j4 < Ccols; j4 += 128) {
            float4 v = *(float4*)&sc[row * SCS + j4];
            s += v.x + v.y + v.z + v.w;
        }
        #pragma unroll
        for (int o = 16; o > 0; o >>= 1) s += __shfl_xor_sync(0xffffffffu, s, o);
        if (lane == 0) invs[row] = 1.f / s;
    }
    __syncthreads();

    float oc[2][4];
    #pragma unroll
    for (int i = 0; i < 2; i++)
        #pragma unroll
        for (int j = 0; j < 4; j++) oc[i][j] = 0.f;

    if (warp < 8) {
        // ---- w-store half ----
        #pragma unroll
        for (int rr = 0; rr < 4; rr++) {
            int row = warp * 4 + rr;
            float inv = invs[row];
            size_t wb = ((size_t)(bh * Sx + q0 + row)) * Sx;
            for (int j4 = lane * 4; j4 < Ccols; j4 += 128) {
                float4 v = *(float4*)&sc[row * SCS + j4];
                float4 o4 = {v.x * inv, v.y * inv, v.z * inv, v.w * inv};
                *(float4*)&w_out[wb + j4] = o4;
            }
            float4 z = {0.f, 0.f, 0.f, 0.f};
            for (int j4 = Ccols + lane * 4; j4 < Sx; j4 += 128)
                *(float4*)&w_out[wb + j4] = z;
        }
    } else {
        // ---- PV half ----
        const int pwm = (warp - 8) >> 2;
        const int pwn = (warp - 8) & 3;

        for (int jt = 0; jt < ntile; jt++) {
            const int j0 = jt * 128;
            if (jt + 1 < ntile) { stageV((jt + 1) & 1, jt + 1); CP_COMMIT(); CP_WAIT1(); }
            else                { CP_WAIT0(); }
            BARP();
            const float* vst = kvb + (jt & 1) * 8192;

            #pragma unroll
            for (int ks = 0; ks < 16; ks++) {
                const int kb = ks * 8;
                unsigned a[4];
                const float* ap0 = &sc[(pwm * 16 + r) * SCS + j0 + kb + cq];
                const float* ap1 = ap0 + 8 * SCS;
                a[0] = __float_as_uint(ap0[0]);
                a[1] = __float_as_uint(ap1[0]);
                a[2] = __float_as_uint(ap0[4]);
                a[3] = __float_as_uint(ap1[4]);
                #pragma unroll
                for (int nn = 0; nn < 2; nn++) {
                    uint2 bv = *(const uint2*)&vst[((pwn * 2 + nn) * 16 + ks) * 64 + lane * 2];
                    unsigned bf[2] = {bv.x, bv.y};
                    mma_tf32(oc[nn], a, bf);
                }
            }
            BARP();
        }
    }
    __syncthreads();

    if (warp >= 8) {
        const int pwm = (warp - 8) >> 2;
        const int pwn = (warp - 8) & 3;
        float ia = invs[pwm * 16 + r], ib = invs[pwm * 16 + r + 8];
        // fp16 A-frag write: Ah[mb][kb16=h*4+pwn][lane][4 regs] = one uint4
        int mb = ((b * Sx + q0) >> 4) + pwm;
        int kb16 = h * 4 + pwn;
        uint4 o;
        o.x = pk(oc[0][0] * ia, oc[0][1] * ia);   // (r,   c16=2cq, 2cq+1)
        o.y = pk(oc[0][2] * ib, oc[0][3] * ib);   // (r+8, same)
        o.z = pk(oc[1][0] * ia, oc[1][1] * ia);   // (r,   c16=2cq+8, +9)
        o.w = pk(oc[1][2] * ib, oc[1][3] * ib);   // (r+8, same)
        *(uint4*)&aoutH[(((size_t)mb * 64 + kb16) * 32 + lane) * 4] = o;
    }
}

// ---------------------------------------------------------------------------
extern "C" void kernel_launch(void* const* d_in, const int* in_sizes, int n_in,
                              void* d_out, int out_size) {
    const float* x      = (const float*)d_in[0];
    const float* mask   = (const float*)d_in[1];
    const float* w_attn = (const float*)d_in[2];
    const float* b_attn = (const float*)d_in[3];
    const float* w_proj = (const float*)d_in[4];
    const float* b_proj = (const float*)d_in[5];

    float* out_a = (float*)d_out;
    float* out_w = (float*)d_out + (size_t)Bx * Sx * Dx;

    float *qkv, *kTf, *vTf;
    unsigned *aoutH, *xah, *wah, *wph;
    cudaGetSymbolAddress((void**)&qkv,   g_qkv);
    cudaGetSymbolAddress((void**)&aoutH, g_aoutH);
    cudaGetSymbolAddress((void**)&xah,   g_xah);
    cudaGetSymbolAddress((void**)&wah,   g_wah);
    cudaGetSymbolAddress((void**)&wph,   g_wph);
    cudaGetSymbolAddress((void**)&kTf,   g_kTf);
    cudaGetSymbolAddress((void**)&vTf,   g_vTf);

    static const int ATTN_SMEM = 52384 * 4;   // 209536 B
    cudaFuncSetAttribute(attn_mma, cudaFuncAttributeMaxDynamicSharedMemorySize, ATTN_SMEM);
    cudaFuncSetAttribute(gemm_h,   cudaFuncAttributeMaxDynamicSharedMemorySize, GEMM_SMEM);

    // fp16 fragment packing (rn rounding fused)
    {
        pack_a_h<<<(Bx * Sx * Dx / 8) / 256, 256>>>(x, xah, Dx);
        pack_b_h<<<(Dx * TDx / 4) / 256, 256>>>(w_attn, wah, Dx, TDx);
        pack_b_h<<<(Dx * Dx / 4) / 256, 256>>>(w_proj, wph, Dx, Dx);
    }
    // K1: qkv = x @ w_attn + b_attn   (fp16 m16n8k16)
    {
        dim3 grid(TDx / 128, (Bx * Sx) / 128);
        gemm_h<<<grid, 256, GEMM_SMEM>>>(xah, wah, b_attn, qkv, Bx * Sx, TDx, Dx);
    }
    // tf32 frag-pack K and V for attention
    {
        prep_kTf<<<(Bx * Hx * Sx * HDx / 2) / 256, 256>>>(qkv, kTf);
        prep_vTf<<<(Bx * Hx * Sx * HDx / 2) / 256, 256>>>(qkv, vTf);
    }
    {
        dim3 grid(Sx / 32, Hx, Bx);
        attn_mma<<<grid, 512, ATTN_SMEM>>>(qkv, kTf, vTf, mask, out_w, aoutH);
    }
    // K3: a = aout @ w_proj + b_proj  (fp16; aout frag-packed by attn)
    {
        dim3 grid(Dx / 128, (Bx * Sx) / 128);
        gemm_h<<<grid, 256, GEMM_SMEM>>>(aoutH, wph, b_proj, out_a, Bx * Sx, Dx, Dx);
    }
}